// round 13
// baseline (speedup 1.0000x reference)
#include <cuda_runtime.h>
#include <cuda_fp16.h>
#include <math.h>
#include <cstdint>

#define BB   32
#define LL   512
#define HH   256
#define NH   8
#define HD   32
#define ITERS 6
#define E_DIM 300
#define LY   513  /* 1 + L */

typedef unsigned long long ull;

// ---------------- scratch (device globals; no allocation) ----------------
__device__ float g_nodes[BB*LL*HH];
__device__ float g_relay[BB*HH];
__device__ float g_ak   [BB*HH];
__device__ float g_av   [BB*HH];
__device__ float g_q2   [BB*HH];
__device__ float g_att2 [BB*HH];
// fp16 activations
__device__ __align__(16) __half g_q16  [BB*LL*HH];
__device__ __align__(16) __half g_k16  [BB*LL*HH];
__device__ __align__(16) __half g_yk16 [BB*LY*HH];
__device__ __align__(16) __half g_yv16 [BB*LY*HH];
__device__ __align__(16) __half g_nln16[BB*LL*HH];
__device__ __align__(16) __half g_att16[BB*LL*HH];
__device__ __align__(16) __half g_y16  [BB*LY*HH];
// fp16 transposed weights (single, rounded): 30 slots of [256 n][256 k]
__device__ __align__(16) __half g_w16[30*65536];
// emb_fc split-transposed (3-pass exact x0): [256 n][320 k]
__device__ __align__(16) __half g_wEh[256*320];
__device__ __align__(16) __half g_wEl[256*320];

// ---------------- helpers ----------------
__device__ __forceinline__ float warpReduceSum(float v) {
#pragma unroll
    for (int o = 16; o > 0; o >>= 1) v += __shfl_xor_sync(0xffffffffu, v, o);
    return v;
}
__device__ __forceinline__ uint32_t smem_to_u32(const void* p) {
    uint32_t a;
    asm("{ .reg .u64 t; cvta.to.shared.u64 t, %1; cvt.u32.u64 %0, t; }" : "=r"(a) : "l"(p));
    return a;
}
__device__ __forceinline__ uint32_t swz(uint32_t x) { return x ^ ((x >> 3) & 0x70); }

__device__ __forceinline__ void ldsm_x4(uint32_t* r, uint32_t addr) {
    asm volatile("ldmatrix.sync.aligned.m8n8.x4.shared.b16 {%0,%1,%2,%3}, [%4];"
                 : "=r"(r[0]), "=r"(r[1]), "=r"(r[2]), "=r"(r[3]) : "r"(addr));
}
__device__ __forceinline__ void ldsm_x2(uint32_t* r, uint32_t addr) {
    asm volatile("ldmatrix.sync.aligned.m8n8.x2.shared.b16 {%0,%1}, [%2];"
                 : "=r"(r[0]), "=r"(r[1]) : "r"(addr));
}
__device__ __forceinline__ void mma_fp16(float* c, const uint32_t* a, const uint32_t* b) {
    asm volatile("mma.sync.aligned.m16n8k16.row.col.f32.f16.f16.f32 "
                 "{%0,%1,%2,%3}, {%4,%5,%6,%7}, {%8,%9}, {%0,%1,%2,%3};"
                 : "+f"(c[0]), "+f"(c[1]), "+f"(c[2]), "+f"(c[3])
                 : "r"(a[0]), "r"(a[1]), "r"(a[2]), "r"(a[3]), "r"(b[0]), "r"(b[1]));
}
__device__ __forceinline__ void split_fp16(float v, __half& h, __half& l) {
    h = __float2half_rn(v);
    l = __float2half_rn(v - __half2float(h));
}
__device__ __forceinline__ void cp_async16(uint32_t dst, const void* src) {
    asm volatile("cp.async.cg.shared.global [%0], [%1], 16;" :: "r"(dst), "l"(src));
}
__device__ __forceinline__ void cp16z(uint32_t dst, const void* src, int sz) {
    asm volatile("cp.async.cg.shared.global [%0], [%1], 16, %2;"
                 :: "r"(dst), "l"(src), "r"(sz));
}
__device__ __forceinline__ void cp_commit() {
    asm volatile("cp.async.commit_group;" ::: "memory");
}
template<int N> __device__ __forceinline__ void cp_wait() {
    asm volatile("cp.async.wait_group %0;" :: "n"(N) : "memory");
}

// ============ HMMA fp16 single-pass GEMM (double-buffered cp.async, 2 blocks/SM) ============
// C[M x 256] = A[M x 256] @ W^T;  A fp16, W fp16 [256 n][256 k].
// emode 0: C16 = fp16(acc + bias)
// emode 2: nodes(fp32) += leaky_relu(acc+bias), masked by data; y fp16 emitted pre-mask
// blockIdx.z==1 -> second problem (w1/b1/C1).
__global__ void __launch_bounds__(256, 2)
gemm_mma_kernel(const __half* __restrict__ A16,
                const __half* __restrict__ w0, const float* __restrict__ b0,
                void* __restrict__ C0,
                const __half* __restrict__ w1, const float* __restrict__ b1,
                void* __restrict__ C1,
                int M, int emode, const int* __restrict__ data,
                __half* __restrict__ y16)
{
    extern __shared__ char smem[];
    const __half* w = w0; const float* bias = b0; void* C = C0;
    if (blockIdx.z == 1) { w = w1; bias = b1; C = C1; }

    const uint32_t sb = smem_to_u32(smem);
    const uint32_t STG = 32768;  // per-stage: A 0 | B 16384
    const int tid = threadIdx.x, lane = tid & 31, wid = tid >> 5;
    const int warpM = wid & 1, warpN = wid >> 1;
    const int m0 = blockIdx.y * 128, n0 = blockIdx.x * 128;
    const int r = tid >> 1, cb2 = (tid & 1);

    float c[4][4][4];
#pragma unroll
    for (int i = 0; i < 4; i++)
#pragma unroll
        for (int j = 0; j < 4; j++)
#pragma unroll
            for (int l = 0; l < 4; l++) c[i][j][l] = 0.f;

    auto do_stage = [&](int kc) {
        const int k0 = kc << 6;
        const uint32_t bufo = (uint32_t)(kc & 1) * STG;
        uint32_t rb = (uint32_t)r * 128u + (uint32_t)cb2 * 64u;
        {
            int grow = m0 + r;
            const __half* srcp = A16 + (size_t)grow * HH + k0 + cb2 * 32;
            int sz = (grow < M) ? 16 : 0;
#pragma unroll
            for (int i = 0; i < 4; i++)
                cp16z(sb + bufo + swz(rb + i * 16u), srcp + i * 8, sz);
        }
        {
            const __half* sh = w + (size_t)(n0 + r) * HH + k0 + cb2 * 32;
#pragma unroll
            for (int i = 0; i < 4; i++)
                cp_async16(sb + bufo + 16384u + swz(rb + i * 16u), sh + i * 8);
        }
        cp_commit();
    };

    do_stage(0);
    do_stage(1);

    for (int kc = 0; kc < 4; kc++) {
        if (kc < 3) cp_wait<1>(); else cp_wait<0>();
        __syncthreads();
        const uint32_t bufo = (uint32_t)(kc & 1) * STG;
#pragma unroll
        for (int ks = 0; ks < 4; ks++) {
            uint32_t a[4][4];
#pragma unroll
            for (int mt = 0; mt < 4; mt++) {
                int row = warpM * 64 + mt * 16 + (lane & 15);
                uint32_t off = swz((uint32_t)row * 128u + ks * 32u + ((lane >> 4) << 4));
                ldsm_x4(a[mt], sb + bufo + off);
            }
            uint32_t bfr[4][2];
#pragma unroll
            for (int nt = 0; nt < 4; nt++) {
                int n = warpN * 32 + nt * 8 + (lane & 7);
                uint32_t off = swz((uint32_t)n * 128u + ks * 32u + (((lane >> 3) & 1) << 4));
                ldsm_x2(bfr[nt], sb + bufo + 16384u + off);
            }
#pragma unroll
            for (int mt = 0; mt < 4; mt++)
#pragma unroll
                for (int nt = 0; nt < 4; nt++)
                    mma_fp16(c[mt][nt], a[mt], bfr[nt]);
        }
        __syncthreads();
        if (kc + 2 < 4) do_stage(kc + 2);
    }

    // ---- epilogue ----
    const int gid = lane >> 2, tig = lane & 3;
#pragma unroll
    for (int mt = 0; mt < 4; mt++)
#pragma unroll
        for (int nt = 0; nt < 4; nt++) {
            int col = n0 + warpN * 32 + nt * 8 + tig * 2;
            float bc0 = bias[col], bc1 = bias[col + 1];
#pragma unroll
            for (int h = 0; h < 2; h++) {
                int row = m0 + warpM * 64 + mt * 16 + gid + h * 8;
                if (row >= M) continue;
                float v0 = c[mt][nt][h * 2 + 0] + bc0;
                float v1 = c[mt][nt][h * 2 + 1] + bc1;
                if (emode == 2) {
                    float* crow = (float*)C + (size_t)row * HH + col;
                    float l0 = v0 > 0.f ? v0 : 0.01f * v0;
                    float l1 = v1 > 0.f ? v1 : 0.01f * v1;
                    float n0v = crow[0] + l0;
                    float n1v = crow[1] + l1;
                    bool z = (data[row] == 1);
                    *(float2*)crow = z ? make_float2(0.f, 0.f) : make_float2(n0v, n1v);
                    int b = row >> 9, ll = row & (LL - 1);
                    size_t yo = (size_t)(b * LY + 1 + ll) * HH + col;
                    *(__half2*)(y16 + yo) = __halves2half2(__float2half_rn(n0v),
                                                          __float2half_rn(n1v));
                } else {
                    *(__half2*)((__half*)C + (size_t)row * HH + col) =
                        __halves2half2(__float2half_rn(v0), __float2half_rn(v1));
                }
            }
        }
}

// ============ embedding HMMA GEMM (3-pass split-fp16, exact x0) ============
__global__ void __launch_bounds__(256, 2)
gemm_emb_mma_kernel(const int* __restrict__ data, const float* __restrict__ emb,
                    const __half* __restrict__ whE, const __half* __restrict__ wlE,
                    const float* __restrict__ bias, const float* __restrict__ pos,
                    float* __restrict__ C)
{
    extern __shared__ char smem[];
    const uint32_t sb = smem_to_u32(smem);
    const int tid = threadIdx.x, lane = tid & 31, wid = tid >> 5;
    const int warpM = wid & 1, warpN = wid >> 1;
    const int m0 = blockIdx.y * 128, n0 = blockIdx.x * 128;
    const int half = tid >> 7, r = tid & 127;

    float c[4][4][4];
#pragma unroll
    for (int i = 0; i < 4; i++)
#pragma unroll
        for (int j = 0; j < 4; j++)
#pragma unroll
            for (int l = 0; l < 4; l++) c[i][j][l] = 0.f;

    for (int kc = 0; kc < 5; kc++) {
        const int k0 = kc << 6;
        {
            int grow = m0 + r;
            const float* srow = emb + (size_t)data[grow] * E_DIM;
            char* dbase = smem + half * 16384;
            uint32_t rb = (uint32_t)r * 128u;
#pragma unroll
            for (int i = 0; i < 8; i++) {
                union { uint4 u; unsigned short s[8]; } pk;
#pragma unroll
                for (int j = 0; j < 8; j++) {
                    int kk = k0 + i * 8 + j;
                    float f = (kk < E_DIM) ? srow[kk] : 0.f;
                    __half h, l;
                    split_fp16(f, h, l);
                    pk.s[j] = __half_as_ushort(half ? l : h);
                }
                *(uint4*)(dbase + swz(rb + i * 16u)) = pk.u;
            }
        }
        {
            const __half* srcp = (half ? wlE : whE) + (size_t)(n0 + r) * 320 + k0;
            char* dbase = smem + 32768 + half * 16384;
            uint32_t rb = (uint32_t)r * 128u;
#pragma unroll
            for (int i = 0; i < 8; i++)
                *(uint4*)(dbase + swz(rb + i * 16u)) = *(const uint4*)(srcp + i * 8);
        }
        __syncthreads();
#pragma unroll
        for (int ks = 0; ks < 4; ks++) {
            uint32_t ah[4][4], al[4][4];
#pragma unroll
            for (int mt = 0; mt < 4; mt++) {
                int row = warpM * 64 + mt * 16 + (lane & 15);
                uint32_t off = swz((uint32_t)row * 128u + ks * 32u + ((lane >> 4) << 4));
                ldsm_x4(ah[mt], sb + off);
                ldsm_x4(al[mt], sb + 16384u + off);
            }
            uint32_t bh[4][2], bl[4][2];
#pragma unroll
            for (int nt = 0; nt < 4; nt++) {
                int n = warpN * 32 + nt * 8 + (lane & 7);
                uint32_t off = swz((uint32_t)n * 128u + ks * 32u + (((lane >> 3) & 1) << 4));
                ldsm_x2(bh[nt], sb + 32768u + off);
                ldsm_x2(bl[nt], sb + 49152u + off);
            }
#pragma unroll
            for (int mt = 0; mt < 4; mt++)
#pragma unroll
                for (int nt = 0; nt < 4; nt++) {
                    mma_fp16(c[mt][nt], ah[mt], bh[nt]);
                    mma_fp16(c[mt][nt], ah[mt], bl[nt]);
                    mma_fp16(c[mt][nt], al[mt], bh[nt]);
                }
        }
        __syncthreads();
    }

    const int gid = lane >> 2, tig = lane & 3;
#pragma unroll
    for (int mt = 0; mt < 4; mt++)
#pragma unroll
        for (int nt = 0; nt < 4; nt++) {
            int col = n0 + warpN * 32 + nt * 8 + tig * 2;
            float bc0 = bias[col], bc1 = bias[col + 1];
#pragma unroll
            for (int h = 0; h < 2; h++) {
                int row = m0 + warpM * 64 + mt * 16 + gid + h * 8;
                int pr = (row & (LL - 1)) * HH + col;
                float v0 = c[mt][nt][h * 2 + 0] + bc0 + pos[pr];
                float v1 = c[mt][nt][h * 2 + 1] + bc1 + pos[pr + 1];
                *(float2*)&C[(size_t)row * HH + col] = make_float2(v0, v1);
            }
        }
}

// ============ weight prep: coalesced tiled transpose + fp16 ============
// grid (8, 10, 31), block (32, 8). slots 0..29: single fp16; slot 30: emb split hi/lo
__global__ void prep_w_kernel(const float* __restrict__ rWQ, const float* __restrict__ rWK,
                              const float* __restrict__ rWO, const float* __restrict__ sWK,
                              const float* __restrict__ sWV, const float* __restrict__ embW,
                              __half* __restrict__ w16,
                              __half* __restrict__ whiE, __half* __restrict__ wloE)
{
    int slot = blockIdx.z;
    int n0 = blockIdx.x * 32, k0 = blockIdx.y * 32;
    __shared__ float tile[32][33];
    int tx = threadIdx.x, ty = threadIdx.y;
    if (slot < 30) {
        if (k0 >= 256) return;
        int fam = slot / 6, it = slot % 6;
        const float* W = (fam == 0 ? rWQ : fam == 1 ? rWK : fam == 2 ? rWO :
                          fam == 3 ? sWK : sWV) + (size_t)it * HH * HH;
        __half* oh = w16 + (size_t)slot * 65536;
#pragma unroll
        for (int i = 0; i < 4; i++)
            tile[ty + i * 8][tx] = W[(size_t)(k0 + ty + i * 8) * HH + n0 + tx];
        __syncthreads();
#pragma unroll
        for (int i = 0; i < 4; i++) {
            int n = n0 + ty + i * 8;
            oh[(size_t)n * HH + k0 + tx] = __float2half_rn(tile[tx][ty + i * 8]);
        }
    } else {
#pragma unroll
        for (int i = 0; i < 4; i++) {
            int k = k0 + ty + i * 8;
            tile[ty + i * 8][tx] = (k < E_DIM) ? embW[(size_t)k * HH + n0 + tx] : 0.f;
        }
        __syncthreads();
#pragma unroll
        for (int i = 0; i < 4; i++) {
            int n = n0 + ty + i * 8;
            float x = tile[tx][ty + i * 8];
            __half h, l;
            split_fp16(x, h, l);
            size_t o = (size_t)n * 320 + k0 + tx;
            whiE[o] = h; wloE[o] = l;
        }
    }
}

// ---------------- layernorm: one warp per row -> fp16 out ----------------
__global__ void __launch_bounds__(256)
layernorm_kernel(const float* __restrict__ x, __half* __restrict__ y16,
                 const float* __restrict__ g, const float* __restrict__ b)
{
    int w = threadIdx.x >> 5, lane = threadIdx.x & 31;
    int row = blockIdx.x * 8 + w;
    const float* xr = x + (size_t)row * HH;
    float4 v0 = *(const float4*)&xr[lane * 4];
    float4 v1 = *(const float4*)&xr[lane * 4 + 128];
    float s = v0.x + v0.y + v0.z + v0.w + v1.x + v1.y + v1.z + v1.w;
    float mean = warpReduceSum(s) * (1.f / HH);
    float d[8] = { v0.x - mean, v0.y - mean, v0.z - mean, v0.w - mean,
                   v1.x - mean, v1.y - mean, v1.z - mean, v1.w - mean };
    float s2 = 0.f;
#pragma unroll
    for (int i = 0; i < 8; i++) s2 += d[i] * d[i];
    float var = warpReduceSum(s2) * (1.f / HH);
    float rs = rsqrtf(var + 1e-5f);
    float4 g0 = *(const float4*)&g[lane * 4];
    float4 g1 = *(const float4*)&g[lane * 4 + 128];
    float4 bb0 = *(const float4*)&b[lane * 4];
    float4 bb1 = *(const float4*)&b[lane * 4 + 128];
    float o[8] = { g0.x*d[0]*rs + bb0.x, g0.y*d[1]*rs + bb0.y,
                   g0.z*d[2]*rs + bb0.z, g0.w*d[3]*rs + bb0.w,
                   g1.x*d[4]*rs + bb1.x, g1.y*d[5]*rs + bb1.y,
                   g1.z*d[6]*rs + bb1.z, g1.w*d[7]*rs + bb1.w };
#pragma unroll
    for (int seg = 0; seg < 2; seg++) {
        ushort4 hv;
        hv.x = __half_as_ushort(__float2half_rn(o[seg*4+0]));
        hv.y = __half_as_ushort(__float2half_rn(o[seg*4+1]));
        hv.z = __half_as_ushort(__float2half_rn(o[seg*4+2]));
        hv.w = __half_as_ushort(__float2half_rn(o[seg*4+3]));
        *(ushort4*)(y16 + (size_t)row * HH + lane * 4 + seg * 128) = hv;
    }
}

// ---------------- relay = mean over L ----------------
__global__ void __launch_bounds__(256)
relay_mean_kernel(const float* __restrict__ x0, float* __restrict__ relay)
{
    int b = blockIdx.x;
    int tx = threadIdx.x & 63, ty = threadIdx.x >> 6;
    float4 acc = make_float4(0.f, 0.f, 0.f, 0.f);
    for (int l = ty; l < LL; l += 4) {
        float4 v = *(const float4*)&x0[(size_t)(b * LL + l) * HH + tx * 4];
        acc.x += v.x; acc.y += v.y; acc.z += v.z; acc.w += v.w;
    }
    __shared__ float4 part[4][64];
    part[ty][tx] = acc;
    __syncthreads();
    if (ty == 0) {
        float4 s = part[0][tx];
#pragma unroll
        for (int i = 1; i < 4; i++) {
            s.x += part[i][tx].x; s.y += part[i][tx].y;
            s.z += part[i][tx].z; s.w += part[i][tx].w;
        }
        const float inv = 1.f / LL;
        *(float4*)&relay[b * HH + tx * 4] =
            make_float4(s.x * inv, s.y * inv, s.z * inv, s.w * inv);
    }
}

// ---------------- fused relay projections: ak, av, q2, y-row ----------------
__global__ void __launch_bounds__(256)
rowproj4_kernel(const float* __restrict__ relay,
                const float* __restrict__ WK, const float* __restrict__ bK, float* __restrict__ ak,
                const float* __restrict__ WV, const float* __restrict__ bV, float* __restrict__ av,
                const float* __restrict__ sWQ, const float* __restrict__ sbQ, float* __restrict__ q2,
                __half* __restrict__ y16)
{
    int seg = blockIdx.x >> 5, b = blockIdx.x & 31, t = threadIdx.x;
    if (seg == 3) {
        y16[(size_t)(b * LY) * HH + t] = __float2half_rn(relay[b * HH + t]);
        return;
    }
    const float* W  = seg == 0 ? WK : seg == 1 ? WV : sWQ;
    const float* bi = seg == 0 ? bK : seg == 1 ? bV : sbQ;
    float* o        = seg == 0 ? ak : seg == 1 ? av : q2;
    __shared__ float xin[HH];
    xin[t] = relay[b * HH + t];
    __syncthreads();
    float s = bi[t];
#pragma unroll 8
    for (int k = 0; k < HH; k++) s += xin[k] * W[k * HH + t];
    o[b * HH + t] = s;
}

__global__ void rowproj_kernel(const float* __restrict__ in, const float* __restrict__ W,
                               const float* __restrict__ bias, float* __restrict__ out,
                               int lrelu)
{
    __shared__ float xin[HH];
    int b = blockIdx.x, t = threadIdx.x;
    xin[t] = in[b * HH + t];
    __syncthreads();
    float s = bias[t];
#pragma unroll 8
    for (int k = 0; k < HH; k++) s += xin[k] * W[k * HH + t];
    if (lrelu) s = s > 0.f ? s : 0.01f * s;
    out[b * HH + t] = s;
}

// ---------------- msa1: 8 rows/block, smem-staged sliding k window ----------------
__global__ void __launch_bounds__(256)
msa1_attn_kernel(const __half* __restrict__ q16, const __half* __restrict__ k16,
                 const float* __restrict__ ak, const float* __restrict__ av,
                 __half* __restrict__ att16)
{
    __shared__ __half ks[10][HH];
    __shared__ __half qs[8][HH];
    __shared__ float aks[HH], avs[HH];
    int r0 = blockIdx.x * 8;
    int b = r0 >> 9, l0 = r0 & (LL - 1);
    int t = threadIdx.x;
    for (int id = t; id < 10 * 128; id += 256) {
        int i = id >> 7, cu = id & 127;
        int gr = r0 - 1 + i;
        gr = gr < 0 ? 0 : (gr > BB * LL - 1 ? BB * LL - 1 : gr);
        ((uint32_t*)ks[i])[cu] = ((const uint32_t*)(k16 + (size_t)gr * HH))[cu];
    }
    for (int id = t; id < 8 * 128; id += 256) {
        int i = id >> 7, cu = id & 127;
        ((uint32_t*)qs[i])[cu] = ((const uint32_t*)(q16 + (size_t)(r0 + i) * HH))[cu];
    }
    aks[t] = ak[b * HH + t];
    avs[t] = av[b * HH + t];
    __syncthreads();
    int c = t;
    float akv = aks[c], avv = avs[c];
    const float sc = 0.17677669529663687f;
#pragma unroll
    for (int rr = 0; rr < 8; rr++) {
        int l = l0 + rr;
        float qv  = __half2float(qs[rr][c]);
        float k0v = __half2float(ks[rr + 1][c]);
        float kmv = (l > 0)      ? __half2float(ks[rr][c])     : 0.f;
        float kpv = (l < LL - 1) ? __half2float(ks[rr + 2][c]) : 0.f;
        float s0 = warpReduceSum(qv * akv) * sc;
        float s1 = warpReduceSum(qv * kmv) * sc;
        float s2 = warpReduceSum(qv * k0v) * sc;
        float s3 = warpReduceSum(qv * kpv) * sc;
        float m = fmaxf(fmaxf(s0, s1), fmaxf(s2, s3));
        float e0 = expf(s0 - m), e1 = expf(s1 - m), e2 = expf(s2 - m), e3 = expf(s3 - m);
        float inv = 1.f / (e0 + e1 + e2 + e3);
        float o = (e0 * avv + e1 * kmv + e2 * k0v + e3 * kpv) * inv;
        att16[(size_t)(r0 + rr) * HH + c] = __float2half_rn(o);
    }
}

// ---------------- msa2 (fp16 yk/yv) ----------------
__global__ void __launch_bounds__(256)
msa2_attn_kernel(const float* __restrict__ q2, const __half* __restrict__ yk,
                 const __half* __restrict__ yv, float* __restrict__ att2)
{
    __shared__ float sc[LY];
    __shared__ float red[8];
    __shared__ float part[8][HD];
    int b = blockIdx.x >> 3, h = blockIdx.x & 7;
    int t = threadIdx.x, w = t >> 5, d = t & 31;
    const float scale = 0.17677669529663687f;
    float qv = q2[b * HH + h * HD + d];
    const __half* kb = yk + (size_t)b * LY * HH + h * HD;
    const __half* vb = yv + (size_t)b * LY * HH + h * HD;
    for (int l = w; l < LY; l += 8) {
        float s = warpReduceSum(qv * __half2float(kb[(size_t)l * HH + d])) * scale;
        if (d == 0) sc[l] = s;
    }
    __syncthreads();
    float m = -3.4e38f;
    for (int l = t; l < LY; l += 256) m = fmaxf(m, sc[l]);
#pragma unroll
    for (int o = 16; o > 0; o >>= 1) m = fmaxf(m, __shfl_xor_sync(0xffffffffu, m, o));
    if (d == 0) red[w] = m;
    __syncthreads();
    float mm = red[0];
#pragma unroll
    for (int i = 1; i < 8; i++) mm = fmaxf(mm, red[i]);
    __syncthreads();
    float ssum = 0.f;
    for (int l = t; l < LY; l += 256) { float e = expf(sc[l] - mm); sc[l] = e; ssum += e; }
    ssum = warpReduceSum(ssum);
    if (d == 0) red[w] = ssum;
    __syncthreads();
    float tot = 0.f;
#pragma unroll
    for (int i = 0; i < 8; i++) tot += red[i];
    float acc = 0.f;
    for (int l = w; l < LY; l += 8) acc += sc[l] * __half2float(vb[(size_t)l * HH + d]);
    part[w][d] = acc;
    __syncthreads();
    if (w == 0) {
        float o = 0.f;
#pragma unroll
        for (int i = 0; i < 8; i++) o += part[i][d];
        att2[b * HH + h * HD + d] = o / tot;
    }
}

// ---------------- final: 0.5*max_l(nodes) + 0.5*relay ----------------
__global__ void __launch_bounds__(256)
final_kernel(const float* __restrict__ nodes, const float* __restrict__ relay,
             float* __restrict__ out)
{
    int b = blockIdx.x;
    int tx = threadIdx.x & 63, ty = threadIdx.x >> 6;
    float4 m = make_float4(-3.4e38f, -3.4e38f, -3.4e38f, -3.4e38f);
    for (int l = ty; l < LL; l += 4) {
        float4 v = *(const float4*)&nodes[(size_t)(b * LL + l) * HH + tx * 4];
        m.x = fmaxf(m.x, v.x); m.y = fmaxf(m.y, v.y);
        m.z = fmaxf(m.z, v.z); m.w = fmaxf(m.w, v.w);
    }
    __shared__ float4 part[4][64];
    part[ty][tx] = m;
    __syncthreads();
    if (ty == 0) {
        float4 s = part[0][tx];
#pragma unroll
        for (int i = 1; i < 4; i++) {
            s.x = fmaxf(s.x, part[i][tx].x); s.y = fmaxf(s.y, part[i][tx].y);
            s.z = fmaxf(s.z, part[i][tx].z); s.w = fmaxf(s.w, part[i][tx].w);
        }
        float4 r = *(const float4*)&relay[b * HH + tx * 4];
        *(float4*)&out[b * HH + tx * 4] =
            make_float4(0.5f * s.x + 0.5f * r.x, 0.5f * s.y + 0.5f * r.y,
                        0.5f * s.z + 0.5f * r.z, 0.5f * s.w + 0.5f * r.w);
    }
}

// ---------------- host ----------------
extern "C" void kernel_launch(void* const* d_in, const int* in_sizes, int n_in,
                              void* d_out, int out_size)
{
    const int*   data     = (const int*)  d_in[0];
    const float* emb      = (const float*)d_in[1];
    const float* emb_fc_W = (const float*)d_in[2];
    const float* emb_fc_b = (const float*)d_in[3];
    const float* pos_emb  = (const float*)d_in[4];
    const float* ln_g     = (const float*)d_in[5];
    const float* ln_b     = (const float*)d_in[6];
    const float* r_WQ = (const float*)d_in[7];
    const float* r_bQ = (const float*)d_in[8];
    const float* r_WK = (const float*)d_in[9];
    const float* r_bK = (const float*)d_in[10];
    const float* r_WV = (const float*)d_in[11];
    const float* r_bV = (const float*)d_in[12];
    const float* r_WO = (const float*)d_in[13];
    const float* r_bO = (const float*)d_in[14];
    const float* s_WQ = (const float*)d_in[15];
    const float* s_bQ = (const float*)d_in[16];
    const float* s_WK = (const float*)d_in[17];
    const float* s_bK = (const float*)d_in[18];
    const float* s_WV = (const float*)d_in[19];
    const float* s_bV = (const float*)d_in[20];
    const float* s_WO = (const float*)d_in[21];
    const float* s_bO = (const float*)d_in[22];
    float* out = (float*)d_out;
    (void)in_sizes; (void)n_in; (void)out_size;

    float *nodes, *relay, *ak, *av, *q2, *att2;
    __half *q16, *k16, *yk16, *yv16;
    __half *w16, *wEh, *wEl, *nln16, *att16, *y16;
    cudaGetSymbolAddress((void**)&nodes, g_nodes);
    cudaGetSymbolAddress((void**)&relay, g_relay);
    cudaGetSymbolAddress((void**)&ak,    g_ak);
    cudaGetSymbolAddress((void**)&av,    g_av);
    cudaGetSymbolAddress((void**)&q2,    g_q2);
    cudaGetSymbolAddress((void**)&att2,  g_att2);
    cudaGetSymbolAddress((void**)&q16,   g_q16);
    cudaGetSymbolAddress((void**)&k16,   g_k16);
    cudaGetSymbolAddress((void**)&yk16,  g_yk16);
    cudaGetSymbolAddress((void**)&yv16,  g_yv16);
    cudaGetSymbolAddress((void**)&w16,   g_w16);
    cudaGetSymbolAddress((void**)&wEh,   g_wEh);
    cudaGetSymbolAddress((void**)&wEl,   g_wEl);
    cudaGetSymbolAddress((void**)&nln16, g_nln16);
    cudaGetSymbolAddress((void**)&att16, g_att16);
    cudaGetSymbolAddress((void**)&y16,   g_y16);

    const int M1 = BB * LL;    // 16384
    const int M2 = BB * LY;    // 16416
    const int MMA_SMEM  = 65536;   // 2 x 32KB stages -> 2 blocks/SM
    const int EMB_SMEM  = 65536;
    static int attr_done = 0;
    if (!attr_done) {
        cudaFuncSetAttribute(gemm_mma_kernel,
                             cudaFuncAttributeMaxDynamicSharedMemorySize, MMA_SMEM);
        cudaFuncSetAttribute(gemm_emb_mma_kernel,
                             cudaFuncAttributeMaxDynamicSharedMemorySize, EMB_SMEM);
        attr_done = 1;
    }

    dim3 blk(256);
    auto WS = [&](int slot) { return w16 + (size_t)slot * 65536; };

    // prep fp16 transposed weights (Q=0..5, K=6..11, O=12..17, sK=18..23, sV=24..29, emb=30)
    prep_w_kernel<<<dim3(8, 10, 31), dim3(32, 8)>>>(r_WQ, r_WK, r_WO, s_WK, s_WV, emb_fc_W,
                                                    w16, wEh, wEl);

    // x0 = emb[data] @ emb_fc_W + b + pos ; relay = mean_L(x0)
    gemm_emb_mma_kernel<<<dim3(2, 128), blk, EMB_SMEM>>>(data, emb, wEh, wEl,
                                                         emb_fc_b, pos_emb, nodes);
    relay_mean_kernel<<<BB, blk>>>(nodes, relay);

    for (int i = 0; i < ITERS; i++) {
        const float* bQ = r_bQ + i * HH;
        const float* bK = r_bK + i * HH;
        const float* WK = r_WK + i * HH * HH;
        const float* WV = r_WV + i * HH * HH;
        const float* bV = r_bV + i * HH;
        const float* bO = r_bO + i * HH;
        const float* sWQ = s_WQ + i * HH * HH; const float* sbQ = s_bQ + i * HH;
        const float* sbK = s_bK + i * HH;
        const float* sbV = s_bV + i * HH;
        const float* sWO = s_WO + i * HH * HH; const float* sbO = s_bO + i * HH;

        layernorm_kernel<<<M1 / 8, blk>>>(nodes, nln16, ln_g + i * HH, ln_b + i * HH);
        // fused Q + K projections (single-pass fp16)
        gemm_mma_kernel<<<dim3(2, 128, 2), blk, MMA_SMEM>>>(
            nln16, WS(i), bQ, q16, WS(6 + i), bK, k16,
            M1, 0, nullptr, nullptr);
        // fused ak + av + q2 + relay->y row (exact fp32)
        rowproj4_kernel<<<4 * BB, blk>>>(relay, WK, bK, ak, WV, bV, av,
                                         sWQ, sbQ, q2, y16);
        msa1_attn_kernel<<<M1 / 8, blk>>>(q16, k16, ak, av, att16);
        // O projection + leaky residual + mask + y emit
        gemm_mma_kernel<<<dim3(2, 128, 1), blk, MMA_SMEM>>>(
            att16, WS(12 + i), bO, nodes,
            nullptr, nullptr, nullptr,
            M1, 2, data, y16);
        // fused yK + yV
        gemm_mma_kernel<<<dim3(2, 129, 2), blk, MMA_SMEM>>>(
            y16, WS(18 + i), sbK, yk16,
            WS(24 + i), sbV, yv16,
            M2, 0, nullptr, nullptr);
        msa2_attn_kernel<<<BB * NH, blk>>>(q2, yk16, yv16, att2);
        rowproj_kernel<<<BB, HH>>>(att2, sWO, sbO, relay, 1);
    }
    final_kernel<<<BB, blk>>>(nodes, relay, out);
}

// round 14
// speedup vs baseline: 1.2071x; 1.2071x over previous
#include <cuda_runtime.h>
#include <cuda_fp16.h>
#include <math.h>
#include <cstdint>

#define BB   32
#define LL   512
#define HH   256
#define NH   8
#define HD   32
#define ITERS 6
#define E_DIM 300
#define LY   513  /* 1 + L */

typedef unsigned long long ull;

// ---------------- scratch (device globals; no allocation) ----------------
__device__ float g_nodes[BB*LL*HH];
__device__ float g_relay[BB*HH];
__device__ float g_ak   [BB*HH];
__device__ float g_av   [BB*HH];
__device__ float g_q2   [BB*HH];
__device__ float g_att2 [BB*HH];
// fp16 activations
__device__ __align__(16) __half g_q16  [BB*LL*HH];
__device__ __align__(16) __half g_k16  [BB*LL*HH];
__device__ __align__(16) __half g_yk16 [BB*LY*HH];
__device__ __align__(16) __half g_yv16 [BB*LY*HH];
__device__ __align__(16) __half g_nln16[BB*LL*HH];
__device__ __align__(16) __half g_att16[BB*LL*HH];
__device__ __align__(16) __half g_y16  [BB*LY*HH];
// split-fp16 transposed weights: 30 slots of [256 n][256 k]
__device__ __align__(16) __half g_w16h[30*65536];
__device__ __align__(16) __half g_w16l[30*65536];
// emb_fc split-transposed: [256 n][320 k] (zero-padded k>=300)
__device__ __align__(16) __half g_wEh[256*320];
__device__ __align__(16) __half g_wEl[256*320];

// ---------------- helpers ----------------
__device__ __forceinline__ float warpReduceSum(float v) {
#pragma unroll
    for (int o = 16; o > 0; o >>= 1) v += __shfl_xor_sync(0xffffffffu, v, o);
    return v;
}
__device__ __forceinline__ uint32_t smem_to_u32(const void* p) {
    uint32_t a;
    asm("{ .reg .u64 t; cvta.to.shared.u64 t, %1; cvt.u32.u64 %0, t; }" : "=r"(a) : "l"(p));
    return a;
}
__device__ __forceinline__ uint32_t swz(uint32_t x) { return x ^ ((x >> 3) & 0x70); }

__device__ __forceinline__ void ldsm_x4(uint32_t* r, uint32_t addr) {
    asm volatile("ldmatrix.sync.aligned.m8n8.x4.shared.b16 {%0,%1,%2,%3}, [%4];"
                 : "=r"(r[0]), "=r"(r[1]), "=r"(r[2]), "=r"(r[3]) : "r"(addr));
}
__device__ __forceinline__ void ldsm_x2(uint32_t* r, uint32_t addr) {
    asm volatile("ldmatrix.sync.aligned.m8n8.x2.shared.b16 {%0,%1}, [%2];"
                 : "=r"(r[0]), "=r"(r[1]) : "r"(addr));
}
__device__ __forceinline__ void mma_fp16(float* c, const uint32_t* a, const uint32_t* b) {
    asm volatile("mma.sync.aligned.m16n8k16.row.col.f32.f16.f16.f32 "
                 "{%0,%1,%2,%3}, {%4,%5,%6,%7}, {%8,%9}, {%0,%1,%2,%3};"
                 : "+f"(c[0]), "+f"(c[1]), "+f"(c[2]), "+f"(c[3])
                 : "r"(a[0]), "r"(a[1]), "r"(a[2]), "r"(a[3]), "r"(b[0]), "r"(b[1]));
}
__device__ __forceinline__ void split_fp16(float v, __half& h, __half& l) {
    h = __float2half_rn(v);
    l = __float2half_rn(v - __half2float(h));
}
__device__ __forceinline__ void cp_async16(uint32_t dst, const void* src) {
    asm volatile("cp.async.cg.shared.global [%0], [%1], 16;" :: "r"(dst), "l"(src));
}
__device__ __forceinline__ void cp16z(uint32_t dst, const void* src, int sz) {
    asm volatile("cp.async.cg.shared.global [%0], [%1], 16, %2;"
                 :: "r"(dst), "l"(src), "r"(sz));
}
__device__ __forceinline__ void cp_commit() {
    asm volatile("cp.async.commit_group;" ::: "memory");
}
template<int N> __device__ __forceinline__ void cp_wait() {
    asm volatile("cp.async.wait_group %0;" :: "n"(N) : "memory");
}

// ============ HMMA fp16 2-pass GEMM (double-buffered cp.async, 2 blocks/SM) ============
// C[M x 256] = A[M x 256] @ (Wh + Wl)^T;  A fp16, W split fp16 [256 n][256 k].
// emode 0: C16 = fp16(acc + bias)
// emode 2: nodes(fp32) += leaky_relu(acc+bias), masked by data; y fp16 emitted pre-mask
// blockIdx.z==1 -> second problem.
__global__ void __launch_bounds__(256, 2)
gemm_mma_kernel(const __half* __restrict__ A16,
                const __half* __restrict__ wh0, const __half* __restrict__ wl0,
                const float* __restrict__ b0, void* __restrict__ C0,
                const __half* __restrict__ wh1, const __half* __restrict__ wl1,
                const float* __restrict__ b1, void* __restrict__ C1,
                int M, int emode, const int* __restrict__ data,
                __half* __restrict__ y16)
{
    extern __shared__ char smem[];
    const __half* wh = wh0; const __half* wl = wl0;
    const float* bias = b0; void* C = C0;
    if (blockIdx.z == 1) { wh = wh1; wl = wl1; bias = b1; C = C1; }

    const uint32_t sb = smem_to_u32(smem);
    const uint32_t STG = 49152;  // per-stage: A 0 | B_HI 16384 | B_LO 32768
    const int tid = threadIdx.x, lane = tid & 31, wid = tid >> 5;
    const int warpM = wid & 1, warpN = wid >> 1;
    const int m0 = blockIdx.y * 128, n0 = blockIdx.x * 128;
    const int r = tid >> 1, cb2 = (tid & 1);

    float c[4][4][4];
#pragma unroll
    for (int i = 0; i < 4; i++)
#pragma unroll
        for (int j = 0; j < 4; j++)
#pragma unroll
            for (int l = 0; l < 4; l++) c[i][j][l] = 0.f;

    auto do_stage = [&](int kc) {
        const int k0 = kc << 6;
        const uint32_t bufo = (uint32_t)(kc & 1) * STG;
        uint32_t rb = (uint32_t)r * 128u + (uint32_t)cb2 * 64u;
        {
            int grow = m0 + r;
            const __half* srcp = A16 + (size_t)grow * HH + k0 + cb2 * 32;
            int sz = (grow < M) ? 16 : 0;
#pragma unroll
            for (int i = 0; i < 4; i++)
                cp16z(sb + bufo + swz(rb + i * 16u), srcp + i * 8, sz);
        }
        {
            const __half* sh = wh + (size_t)(n0 + r) * HH + k0 + cb2 * 32;
            const __half* sl = wl + (size_t)(n0 + r) * HH + k0 + cb2 * 32;
#pragma unroll
            for (int i = 0; i < 4; i++) {
                cp_async16(sb + bufo + 16384u + swz(rb + i * 16u), sh + i * 8);
                cp_async16(sb + bufo + 32768u + swz(rb + i * 16u), sl + i * 8);
            }
        }
        cp_commit();
    };

    do_stage(0);
    do_stage(1);

    for (int kc = 0; kc < 4; kc++) {
        if (kc < 3) cp_wait<1>(); else cp_wait<0>();
        __syncthreads();
        const uint32_t bufo = (uint32_t)(kc & 1) * STG;
#pragma unroll
        for (int ks = 0; ks < 4; ks++) {
            uint32_t a[4][4];
#pragma unroll
            for (int mt = 0; mt < 4; mt++) {
                int row = warpM * 64 + mt * 16 + (lane & 15);
                uint32_t off = swz((uint32_t)row * 128u + ks * 32u + ((lane >> 4) << 4));
                ldsm_x4(a[mt], sb + bufo + off);
            }
            uint32_t bh[4][2], bl[4][2];
#pragma unroll
            for (int nt = 0; nt < 4; nt++) {
                int n = warpN * 32 + nt * 8 + (lane & 7);
                uint32_t off = swz((uint32_t)n * 128u + ks * 32u + (((lane >> 3) & 1) << 4));
                ldsm_x2(bh[nt], sb + bufo + 16384u + off);
                ldsm_x2(bl[nt], sb + bufo + 32768u + off);
            }
#pragma unroll
            for (int mt = 0; mt < 4; mt++)
#pragma unroll
                for (int nt = 0; nt < 4; nt++) {
                    mma_fp16(c[mt][nt], a[mt], bh[nt]);
                    mma_fp16(c[mt][nt], a[mt], bl[nt]);
                }
        }
        __syncthreads();
        if (kc + 2 < 4) do_stage(kc + 2);
    }

    // ---- epilogue ----
    const int gid = lane >> 2, tig = lane & 3;
#pragma unroll
    for (int mt = 0; mt < 4; mt++)
#pragma unroll
        for (int nt = 0; nt < 4; nt++) {
            int col = n0 + warpN * 32 + nt * 8 + tig * 2;
            float bc0 = bias[col], bc1 = bias[col + 1];
#pragma unroll
            for (int h = 0; h < 2; h++) {
                int row = m0 + warpM * 64 + mt * 16 + gid + h * 8;
                if (row >= M) continue;
                float v0 = c[mt][nt][h * 2 + 0] + bc0;
                float v1 = c[mt][nt][h * 2 + 1] + bc1;
                if (emode == 2) {
                    float* crow = (float*)C + (size_t)row * HH + col;
                    float l0 = v0 > 0.f ? v0 : 0.01f * v0;
                    float l1 = v1 > 0.f ? v1 : 0.01f * v1;
                    float n0v = crow[0] + l0;
                    float n1v = crow[1] + l1;
                    bool z = (data[row] == 1);
                    *(float2*)crow = z ? make_float2(0.f, 0.f) : make_float2(n0v, n1v);
                    int b = row >> 9, ll = row & (LL - 1);
                    size_t yo = (size_t)(b * LY + 1 + ll) * HH + col;
                    *(__half2*)(y16 + yo) = __halves2half2(__float2half_rn(n0v),
                                                          __float2half_rn(n1v));
                } else {
                    *(__half2*)((__half*)C + (size_t)row * HH + col) =
                        __halves2half2(__float2half_rn(v0), __float2half_rn(v1));
                }
            }
        }
}

// ============ embedding HMMA GEMM (3-pass split-fp16, exact x0) ============
__global__ void __launch_bounds__(256, 2)
gemm_emb_mma_kernel(const int* __restrict__ data, const float* __restrict__ emb,
                    const __half* __restrict__ whE, const __half* __restrict__ wlE,
                    const float* __restrict__ bias, const float* __restrict__ pos,
                    float* __restrict__ C)
{
    extern __shared__ char smem[];
    const uint32_t sb = smem_to_u32(smem);
    const int tid = threadIdx.x, lane = tid & 31, wid = tid >> 5;
    const int warpM = wid & 1, warpN = wid >> 1;
    const int m0 = blockIdx.y * 128, n0 = blockIdx.x * 128;
    const int half = tid >> 7, r = tid & 127;

    float c[4][4][4];
#pragma unroll
    for (int i = 0; i < 4; i++)
#pragma unroll
        for (int j = 0; j < 4; j++)
#pragma unroll
            for (int l = 0; l < 4; l++) c[i][j][l] = 0.f;

    for (int kc = 0; kc < 5; kc++) {
        const int k0 = kc << 6;
        {
            int grow = m0 + r;
            const float* srow = emb + (size_t)data[grow] * E_DIM;
            char* dbase = smem + half * 16384;
            uint32_t rb = (uint32_t)r * 128u;
#pragma unroll
            for (int i = 0; i < 8; i++) {
                union { uint4 u; unsigned short s[8]; } pk;
#pragma unroll
                for (int j = 0; j < 8; j++) {
                    int kk = k0 + i * 8 + j;
                    float f = (kk < E_DIM) ? srow[kk] : 0.f;
                    __half h, l;
                    split_fp16(f, h, l);
                    pk.s[j] = __half_as_ushort(half ? l : h);
                }
                *(uint4*)(dbase + swz(rb + i * 16u)) = pk.u;
            }
        }
        {
            const __half* srcp = (half ? wlE : whE) + (size_t)(n0 + r) * 320 + k0;
            char* dbase = smem + 32768 + half * 16384;
            uint32_t rb = (uint32_t)r * 128u;
#pragma unroll
            for (int i = 0; i < 8; i++)
                *(uint4*)(dbase + swz(rb + i * 16u)) = *(const uint4*)(srcp + i * 8);
        }
        __syncthreads();
#pragma unroll
        for (int ks = 0; ks < 4; ks++) {
            uint32_t ah[4][4], al[4][4];
#pragma unroll
            for (int mt = 0; mt < 4; mt++) {
                int row = warpM * 64 + mt * 16 + (lane & 15);
                uint32_t off = swz((uint32_t)row * 128u + ks * 32u + ((lane >> 4) << 4));
                ldsm_x4(ah[mt], sb + off);
                ldsm_x4(al[mt], sb + 16384u + off);
            }
            uint32_t bh[4][2], bl[4][2];
#pragma unroll
            for (int nt = 0; nt < 4; nt++) {
                int n = warpN * 32 + nt * 8 + (lane & 7);
                uint32_t off = swz((uint32_t)n * 128u + ks * 32u + (((lane >> 3) & 1) << 4));
                ldsm_x2(bh[nt], sb + 32768u + off);
                ldsm_x2(bl[nt], sb + 49152u + off);
            }
#pragma unroll
            for (int mt = 0; mt < 4; mt++)
#pragma unroll
                for (int nt = 0; nt < 4; nt++) {
                    mma_fp16(c[mt][nt], ah[mt], bh[nt]);
                    mma_fp16(c[mt][nt], ah[mt], bl[nt]);
                    mma_fp16(c[mt][nt], al[mt], bh[nt]);
                }
        }
        __syncthreads();
    }

    const int gid = lane >> 2, tig = lane & 3;
#pragma unroll
    for (int mt = 0; mt < 4; mt++)
#pragma unroll
        for (int nt = 0; nt < 4; nt++) {
            int col = n0 + warpN * 32 + nt * 8 + tig * 2;
            float bc0 = bias[col], bc1 = bias[col + 1];
#pragma unroll
            for (int h = 0; h < 2; h++) {
                int row = m0 + warpM * 64 + mt * 16 + gid + h * 8;
                int pr = (row & (LL - 1)) * HH + col;
                float v0 = c[mt][nt][h * 2 + 0] + bc0 + pos[pr];
                float v1 = c[mt][nt][h * 2 + 1] + bc1 + pos[pr + 1];
                *(float2*)&C[(size_t)row * HH + col] = make_float2(v0, v1);
            }
        }
}

// ============ weight prep: coalesced tiled transpose + fp16 split ============
__global__ void prep_w_kernel(const float* __restrict__ rWQ, const float* __restrict__ rWK,
                              const float* __restrict__ rWO, const float* __restrict__ sWK,
                              const float* __restrict__ sWV, const float* __restrict__ embW,
                              __half* __restrict__ whi, __half* __restrict__ wlo,
                              __half* __restrict__ whiE, __half* __restrict__ wloE)
{
    int slot = blockIdx.z;
    int n0 = blockIdx.x * 32, k0 = blockIdx.y * 32;
    const float* W; int K, Kpad;
    __half *oh, *ol;
    if (slot < 30) {
        if (k0 >= 256) return;
        int fam = slot / 6, it = slot % 6;
        W = (fam == 0 ? rWQ : fam == 1 ? rWK : fam == 2 ? rWO :
             fam == 3 ? sWK : sWV) + (size_t)it * HH * HH;
        K = 256; Kpad = 256;
        oh = whi + (size_t)slot * 65536; ol = wlo + (size_t)slot * 65536;
    } else {
        W = embW; K = E_DIM; Kpad = 320; oh = whiE; ol = wloE;
    }
    __shared__ float tile[32][33];
    int tx = threadIdx.x, ty = threadIdx.y;
#pragma unroll
    for (int i = 0; i < 4; i++) {
        int k = k0 + ty + i * 8;
        tile[ty + i * 8][tx] = (k < K) ? W[(size_t)k * HH + n0 + tx] : 0.f;
    }
    __syncthreads();
#pragma unroll
    for (int i = 0; i < 4; i++) {
        int n = n0 + ty + i * 8;
        float x = tile[tx][ty + i * 8];
        __half h, l;
        split_fp16(x, h, l);
        size_t o = (size_t)n * Kpad + k0 + tx;
        oh[o] = h; ol[o] = l;
    }
}

// ---------------- layernorm: one warp per row -> fp16 out ----------------
__global__ void __launch_bounds__(256)
layernorm_kernel(const float* __restrict__ x, __half* __restrict__ y16,
                 const float* __restrict__ g, const float* __restrict__ b)
{
    int w = threadIdx.x >> 5, lane = threadIdx.x & 31;
    int row = blockIdx.x * 8 + w;
    const float* xr = x + (size_t)row * HH;
    float4 v0 = *(const float4*)&xr[lane * 4];
    float4 v1 = *(const float4*)&xr[lane * 4 + 128];
    float s = v0.x + v0.y + v0.z + v0.w + v1.x + v1.y + v1.z + v1.w;
    float mean = warpReduceSum(s) * (1.f / HH);
    float d[8] = { v0.x - mean, v0.y - mean, v0.z - mean, v0.w - mean,
                   v1.x - mean, v1.y - mean, v1.z - mean, v1.w - mean };
    float s2 = 0.f;
#pragma unroll
    for (int i = 0; i < 8; i++) s2 += d[i] * d[i];
    float var = warpReduceSum(s2) * (1.f / HH);
    float rs = rsqrtf(var + 1e-5f);
    float4 g0 = *(const float4*)&g[lane * 4];
    float4 g1 = *(const float4*)&g[lane * 4 + 128];
    float4 bb0 = *(const float4*)&b[lane * 4];
    float4 bb1 = *(const float4*)&b[lane * 4 + 128];
    float o[8] = { g0.x*d[0]*rs + bb0.x, g0.y*d[1]*rs + bb0.y,
                   g0.z*d[2]*rs + bb0.z, g0.w*d[3]*rs + bb0.w,
                   g1.x*d[4]*rs + bb1.x, g1.y*d[5]*rs + bb1.y,
                   g1.z*d[6]*rs + bb1.z, g1.w*d[7]*rs + bb1.w };
#pragma unroll
    for (int seg = 0; seg < 2; seg++) {
        ushort4 hv;
        hv.x = __half_as_ushort(__float2half_rn(o[seg*4+0]));
        hv.y = __half_as_ushort(__float2half_rn(o[seg*4+1]));
        hv.z = __half_as_ushort(__float2half_rn(o[seg*4+2]));
        hv.w = __half_as_ushort(__float2half_rn(o[seg*4+3]));
        *(ushort4*)(y16 + (size_t)row * HH + lane * 4 + seg * 128) = hv;
    }
}

// ---------------- relay = mean over L ----------------
__global__ void __launch_bounds__(256)
relay_mean_kernel(const float* __restrict__ x0, float* __restrict__ relay)
{
    int b = blockIdx.x;
    int tx = threadIdx.x & 63, ty = threadIdx.x >> 6;
    float4 acc = make_float4(0.f, 0.f, 0.f, 0.f);
    for (int l = ty; l < LL; l += 4) {
        float4 v = *(const float4*)&x0[(size_t)(b * LL + l) * HH + tx * 4];
        acc.x += v.x; acc.y += v.y; acc.z += v.z; acc.w += v.w;
    }
    __shared__ float4 part[4][64];
    part[ty][tx] = acc;
    __syncthreads();
    if (ty == 0) {
        float4 s = part[0][tx];
#pragma unroll
        for (int i = 1; i < 4; i++) {
            s.x += part[i][tx].x; s.y += part[i][tx].y;
            s.z += part[i][tx].z; s.w += part[i][tx].w;
        }
        const float inv = 1.f / LL;
        *(float4*)&relay[b * HH + tx * 4] =
            make_float4(s.x * inv, s.y * inv, s.z * inv, s.w * inv);
    }
}

// ---------------- fused relay projections: ak, av, q2, y-row ----------------
__global__ void __launch_bounds__(256)
rowproj4_kernel(const float* __restrict__ relay,
                const float* __restrict__ WK, const float* __restrict__ bK, float* __restrict__ ak,
                const float* __restrict__ WV, const float* __restrict__ bV, float* __restrict__ av,
                const float* __restrict__ sWQ, const float* __restrict__ sbQ, float* __restrict__ q2,
                __half* __restrict__ y16)
{
    int seg = blockIdx.x >> 5, b = blockIdx.x & 31, t = threadIdx.x;
    if (seg == 3) {
        y16[(size_t)(b * LY) * HH + t] = __float2half_rn(relay[b * HH + t]);
        return;
    }
    const float* W  = seg == 0 ? WK : seg == 1 ? WV : sWQ;
    const float* bi = seg == 0 ? bK : seg == 1 ? bV : sbQ;
    float* o        = seg == 0 ? ak : seg == 1 ? av : q2;
    __shared__ float xin[HH];
    xin[t] = relay[b * HH + t];
    __syncthreads();
    float s = bi[t];
#pragma unroll 8
    for (int k = 0; k < HH; k++) s += xin[k] * W[k * HH + t];
    o[b * HH + t] = s;
}

__global__ void rowproj_kernel(const float* __restrict__ in, const float* __restrict__ W,
                               const float* __restrict__ bias, float* __restrict__ out,
                               int lrelu)
{
    __shared__ float xin[HH];
    int b = blockIdx.x, t = threadIdx.x;
    xin[t] = in[b * HH + t];
    __syncthreads();
    float s = bias[t];
#pragma unroll 8
    for (int k = 0; k < HH; k++) s += xin[k] * W[k * HH + t];
    if (lrelu) s = s > 0.f ? s : 0.01f * s;
    out[b * HH + t] = s;
}

// ---------------- msa1: 8 rows/block, smem-staged sliding k window ----------------
__global__ void __launch_bounds__(256)
msa1_attn_kernel(const __half* __restrict__ q16, const __half* __restrict__ k16,
                 const float* __restrict__ ak, const float* __restrict__ av,
                 __half* __restrict__ att16)
{
    __shared__ __half ks[10][HH];
    __shared__ __half qs[8][HH];
    __shared__ float aks[HH], avs[HH];
    int r0 = blockIdx.x * 8;
    int b = r0 >> 9, l0 = r0 & (LL - 1);
    int t = threadIdx.x;
    for (int id = t; id < 10 * 128; id += 256) {
        int i = id >> 7, cu = id & 127;
        int gr = r0 - 1 + i;
        gr = gr < 0 ? 0 : (gr > BB * LL - 1 ? BB * LL - 1 : gr);
        ((uint32_t*)ks[i])[cu] = ((const uint32_t*)(k16 + (size_t)gr * HH))[cu];
    }
    for (int id = t; id < 8 * 128; id += 256) {
        int i = id >> 7, cu = id & 127;
        ((uint32_t*)qs[i])[cu] = ((const uint32_t*)(q16 + (size_t)(r0 + i) * HH))[cu];
    }
    aks[t] = ak[b * HH + t];
    avs[t] = av[b * HH + t];
    __syncthreads();
    int c = t;
    float akv = aks[c], avv = avs[c];
    const float sc = 0.17677669529663687f;
#pragma unroll
    for (int rr = 0; rr < 8; rr++) {
        int l = l0 + rr;
        float qv  = __half2float(qs[rr][c]);
        float k0v = __half2float(ks[rr + 1][c]);
        float kmv = (l > 0)      ? __half2float(ks[rr][c])     : 0.f;
        float kpv = (l < LL - 1) ? __half2float(ks[rr + 2][c]) : 0.f;
        float s0 = warpReduceSum(qv * akv) * sc;
        float s1 = warpReduceSum(qv * kmv) * sc;
        float s2 = warpReduceSum(qv * k0v) * sc;
        float s3 = warpReduceSum(qv * kpv) * sc;
        float m = fmaxf(fmaxf(s0, s1), fmaxf(s2, s3));
        float e0 = expf(s0 - m), e1 = expf(s1 - m), e2 = expf(s2 - m), e3 = expf(s3 - m);
        float inv = 1.f / (e0 + e1 + e2 + e3);
        float o = (e0 * avv + e1 * kmv + e2 * k0v + e3 * kpv) * inv;
        att16[(size_t)(r0 + rr) * HH + c] = __float2half_rn(o);
    }
}

// ---------------- msa2 (fp16 yk/yv) ----------------
__global__ void __launch_bounds__(256)
msa2_attn_kernel(const float* __restrict__ q2, const __half* __restrict__ yk,
                 const __half* __restrict__ yv, float* __restrict__ att2)
{
    __shared__ float sc[LY];
    __shared__ float red[8];
    __shared__ float part[8][HD];
    int b = blockIdx.x >> 3, h = blockIdx.x & 7;
    int t = threadIdx.x, w = t >> 5, d = t & 31;
    const float scale = 0.17677669529663687f;
    float qv = q2[b * HH + h * HD + d];
    const __half* kb = yk + (size_t)b * LY * HH + h * HD;
    const __half* vb = yv + (size_t)b * LY * HH + h * HD;
    for (int l = w; l < LY; l += 8) {
        float s = warpReduceSum(qv * __half2float(kb[(size_t)l * HH + d])) * scale;
        if (d == 0) sc[l] = s;
    }
    __syncthreads();
    float m = -3.4e38f;
    for (int l = t; l < LY; l += 256) m = fmaxf(m, sc[l]);
#pragma unroll
    for (int o = 16; o > 0; o >>= 1) m = fmaxf(m, __shfl_xor_sync(0xffffffffu, m, o));
    if (d == 0) red[w] = m;
    __syncthreads();
    float mm = red[0];
#pragma unroll
    for (int i = 1; i < 8; i++) mm = fmaxf(mm, red[i]);
    __syncthreads();
    float ssum = 0.f;
    for (int l = t; l < LY; l += 256) { float e = expf(sc[l] - mm); sc[l] = e; ssum += e; }
    ssum = warpReduceSum(ssum);
    if (d == 0) red[w] = ssum;
    __syncthreads();
    float tot = 0.f;
#pragma unroll
    for (int i = 0; i < 8; i++) tot += red[i];
    float acc = 0.f;
    for (int l = w; l < LY; l += 8) acc += sc[l] * __half2float(vb[(size_t)l * HH + d]);
    part[w][d] = acc;
    __syncthreads();
    if (w == 0) {
        float o = 0.f;
#pragma unroll
        for (int i = 0; i < 8; i++) o += part[i][d];
        att2[b * HH + h * HD + d] = o / tot;
    }
}

// ---------------- final: 0.5*max_l(nodes) + 0.5*relay ----------------
__global__ void __launch_bounds__(256)
final_kernel(const float* __restrict__ nodes, const float* __restrict__ relay,
             float* __restrict__ out)
{
    int b = blockIdx.x;
    int tx = threadIdx.x & 63, ty = threadIdx.x >> 6;
    float4 m = make_float4(-3.4e38f, -3.4e38f, -3.4e38f, -3.4e38f);
    for (int l = ty; l < LL; l += 4) {
        float4 v = *(const float4*)&nodes[(size_t)(b * LL + l) * HH + tx * 4];
        m.x = fmaxf(m.x, v.x); m.y = fmaxf(m.y, v.y);
        m.z = fmaxf(m.z, v.z); m.w = fmaxf(m.w, v.w);
    }
    __shared__ float4 part[4][64];
    part[ty][tx] = m;
    __syncthreads();
    if (ty == 0) {
        float4 s = part[0][tx];
#pragma unroll
        for (int i = 1; i < 4; i++) {
            s.x = fmaxf(s.x, part[i][tx].x); s.y = fmaxf(s.y, part[i][tx].y);
            s.z = fmaxf(s.z, part[i][tx].z); s.w = fmaxf(s.w, part[i][tx].w);
        }
        float4 r = *(const float4*)&relay[b * HH + tx * 4];
        *(float4*)&out[b * HH + tx * 4] =
            make_float4(0.5f * s.x + 0.5f * r.x, 0.5f * s.y + 0.5f * r.y,
                        0.5f * s.z + 0.5f * r.z, 0.5f * s.w + 0.5f * r.w);
    }
}

// ---------------- host ----------------
extern "C" void kernel_launch(void* const* d_in, const int* in_sizes, int n_in,
                              void* d_out, int out_size)
{
    const int*   data     = (const int*)  d_in[0];
    const float* emb      = (const float*)d_in[1];
    const float* emb_fc_W = (const float*)d_in[2];
    const float* emb_fc_b = (const float*)d_in[3];
    const float* pos_emb  = (const float*)d_in[4];
    const float* ln_g     = (const float*)d_in[5];
    const float* ln_b     = (const float*)d_in[6];
    const float* r_WQ = (const float*)d_in[7];
    const float* r_bQ = (const float*)d_in[8];
    const float* r_WK = (const float*)d_in[9];
    const float* r_bK = (const float*)d_in[10];
    const float* r_WV = (const float*)d_in[11];
    const float* r_bV = (const float*)d_in[12];
    const float* r_WO = (const float*)d_in[13];
    const float* r_bO = (const float*)d_in[14];
    const float* s_WQ = (const float*)d_in[15];
    const float* s_bQ = (const float*)d_in[16];
    const float* s_WK = (const float*)d_in[17];
    const float* s_bK = (const float*)d_in[18];
    const float* s_WV = (const float*)d_in[19];
    const float* s_bV = (const float*)d_in[20];
    const float* s_WO = (const float*)d_in[21];
    const float* s_bO = (const float*)d_in[22];
    float* out = (float*)d_out;
    (void)in_sizes; (void)n_in; (void)out_size;

    float *nodes, *relay, *ak, *av, *q2, *att2;
    __half *q16, *k16, *yk16, *yv16;
    __half *w16h, *w16l, *wEh, *wEl, *nln16, *att16, *y16;
    cudaGetSymbolAddress((void**)&nodes, g_nodes);
    cudaGetSymbolAddress((void**)&relay, g_relay);
    cudaGetSymbolAddress((void**)&ak,    g_ak);
    cudaGetSymbolAddress((void**)&av,    g_av);
    cudaGetSymbolAddress((void**)&q2,    g_q2);
    cudaGetSymbolAddress((void**)&att2,  g_att2);
    cudaGetSymbolAddress((void**)&q16,   g_q16);
    cudaGetSymbolAddress((void**)&k16,   g_k16);
    cudaGetSymbolAddress((void**)&yk16,  g_yk16);
    cudaGetSymbolAddress((void**)&yv16,  g_yv16);
    cudaGetSymbolAddress((void**)&w16h,  g_w16h);
    cudaGetSymbolAddress((void**)&w16l,  g_w16l);
    cudaGetSymbolAddress((void**)&wEh,   g_wEh);
    cudaGetSymbolAddress((void**)&wEl,   g_wEl);
    cudaGetSymbolAddress((void**)&nln16, g_nln16);
    cudaGetSymbolAddress((void**)&att16, g_att16);
    cudaGetSymbolAddress((void**)&y16,   g_y16);

    const int M1 = BB * LL;    // 16384
    const int M2 = BB * LY;    // 16416
    const int MMA_SMEM  = 98304;   // 2 x 48KB stages -> 2 blocks/SM
    const int EMB_SMEM  = 65536;
    static int attr_done = 0;
    if (!attr_done) {
        cudaFuncSetAttribute(gemm_mma_kernel,
                             cudaFuncAttributeMaxDynamicSharedMemorySize, MMA_SMEM);
        cudaFuncSetAttribute(gemm_emb_mma_kernel,
                             cudaFuncAttributeMaxDynamicSharedMemorySize, EMB_SMEM);
        attr_done = 1;
    }

    dim3 blk(256);
    auto WHp = [&](int slot) { return w16h + (size_t)slot * 65536; };
    auto WLp = [&](int slot) { return w16l + (size_t)slot * 65536; };

    // prep split-transposed weights (Q=0..5, K=6..11, O=12..17, sK=18..23, sV=24..29, emb=30)
    prep_w_kernel<<<dim3(8, 10, 31), dim3(32, 8)>>>(r_WQ, r_WK, r_WO, s_WK, s_WV, emb_fc_W,
                                                    w16h, w16l, wEh, wEl);

    // x0 = emb[data] @ emb_fc_W + b + pos ; relay = mean_L(x0)
    gemm_emb_mma_kernel<<<dim3(2, 128), blk, EMB_SMEM>>>(data, emb, wEh, wEl,
                                                         emb_fc_b, pos_emb, nodes);
    relay_mean_kernel<<<BB, blk>>>(nodes, relay);

    for (int i = 0; i < ITERS; i++) {
        const float* bQ = r_bQ + i * HH;
        const float* bK = r_bK + i * HH;
        const float* WK = r_WK + i * HH * HH;
        const float* WV = r_WV + i * HH * HH;
        const float* bV = r_bV + i * HH;
        const float* bO = r_bO + i * HH;
        const float* sWQ = s_WQ + i * HH * HH; const float* sbQ = s_bQ + i * HH;
        const float* sbK = s_bK + i * HH;
        const float* sbV = s_bV + i * HH;
        const float* sWO = s_WO + i * HH * HH; const float* sbO = s_bO + i * HH;

        layernorm_kernel<<<M1 / 8, blk>>>(nodes, nln16, ln_g + i * HH, ln_b + i * HH);
        // fused Q + K projections (2-pass fp16)
        gemm_mma_kernel<<<dim3(2, 128, 2), blk, MMA_SMEM>>>(
            nln16, WHp(i), WLp(i), bQ, q16, WHp(6 + i), WLp(6 + i), bK, k16,
            M1, 0, nullptr, nullptr);
        // fused ak + av + q2 + relay->y row (exact fp32)
        rowproj4_kernel<<<4 * BB, blk>>>(relay, WK, bK, ak, WV, bV, av,
                                         sWQ, sbQ, q2, y16);
        msa1_attn_kernel<<<M1 / 8, blk>>>(q16, k16, ak, av, att16);
        // O projection + leaky residual + mask + y emit
        gemm_mma_kernel<<<dim3(2, 128, 1), blk, MMA_SMEM>>>(
            att16, WHp(12 + i), WLp(12 + i), bO, nodes,
            nullptr, nullptr, nullptr, nullptr,
            M1, 2, data, y16);
        // fused yK + yV
        gemm_mma_kernel<<<dim3(2, 129, 2), blk, MMA_SMEM>>>(
            y16, WHp(18 + i), WLp(18 + i), sbK, yk16,
            WHp(24 + i), WLp(24 + i), sbV, yv16,
            M2, 0, nullptr, nullptr);
        msa2_attn_kernel<<<BB * NH, blk>>>(q2, yk16, yv16, att2);
        rowproj_kernel<<<BB, HH>>>(att2, sWO, sbO, relay, 1);
    }
    final_kernel<<<BB, blk>>>(nodes, relay, out);
}

// round 15
// speedup vs baseline: 1.2538x; 1.0387x over previous
#include <cuda_runtime.h>
#include <cuda_fp16.h>
#include <math.h>
#include <cstdint>

#define BB   32
#define LL   512
#define HH   256
#define NH   8
#define HD   32
#define ITERS 6
#define E_DIM 300
#define LY   513  /* 1 + L */

typedef unsigned long long ull;

// ---------------- scratch (device globals; no allocation) ----------------
__device__ float g_nodes[BB*LL*HH];
__device__ float g_relay[BB*HH];
__device__ float g_ak   [BB*HH];
__device__ float g_av   [BB*HH];
__device__ float g_q2   [BB*HH];
__device__ float g_att2 [BB*HH];
// fp16 activations
__device__ __align__(16) __half g_q16  [BB*LL*HH];
__device__ __align__(16) __half g_k16  [BB*LL*HH];
__device__ __align__(16) __half g_yk16 [BB*LY*HH];
__device__ __align__(16) __half g_yv16 [BB*LY*HH];
__device__ __align__(16) __half g_nln16[BB*LL*HH];
__device__ __align__(16) __half g_att16[BB*LL*HH];
__device__ __align__(16) __half g_y16  [BB*LY*HH];
// split-fp16 transposed weights: 30 slots of [256 n][256 k]
__device__ __align__(16) __half g_w16h[30*65536];
__device__ __align__(16) __half g_w16l[30*65536];
// emb_fc split-transposed: [256 n][320 k] (zero-padded k>=300)
__device__ __align__(16) __half g_wEh[256*320];
__device__ __align__(16) __half g_wEl[256*320];

// ---------------- helpers ----------------
__device__ __forceinline__ float warpReduceSum(float v) {
#pragma unroll
    for (int o = 16; o > 0; o >>= 1) v += __shfl_xor_sync(0xffffffffu, v, o);
    return v;
}
__device__ __forceinline__ uint32_t smem_to_u32(const void* p) {
    uint32_t a;
    asm("{ .reg .u64 t; cvta.to.shared.u64 t, %1; cvt.u32.u64 %0, t; }" : "=r"(a) : "l"(p));
    return a;
}
__device__ __forceinline__ uint32_t swz(uint32_t x) { return x ^ ((x >> 3) & 0x70); }

__device__ __forceinline__ void ldsm_x4(uint32_t* r, uint32_t addr) {
    asm volatile("ldmatrix.sync.aligned.m8n8.x4.shared.b16 {%0,%1,%2,%3}, [%4];"
                 : "=r"(r[0]), "=r"(r[1]), "=r"(r[2]), "=r"(r[3]) : "r"(addr));
}
__device__ __forceinline__ void mma_fp16(float* c, const uint32_t* a, const uint32_t* b) {
    asm volatile("mma.sync.aligned.m16n8k16.row.col.f32.f16.f16.f32 "
                 "{%0,%1,%2,%3}, {%4,%5,%6,%7}, {%8,%9}, {%0,%1,%2,%3};"
                 : "+f"(c[0]), "+f"(c[1]), "+f"(c[2]), "+f"(c[3])
                 : "r"(a[0]), "r"(a[1]), "r"(a[2]), "r"(a[3]), "r"(b[0]), "r"(b[1]));
}
__device__ __forceinline__ void split_fp16(float v, __half& h, __half& l) {
    h = __float2half_rn(v);
    l = __float2half_rn(v - __half2float(h));
}
__device__ __forceinline__ void cp_async16(uint32_t dst, const void* src) {
    asm volatile("cp.async.cg.shared.global [%0], [%1], 16;" :: "r"(dst), "l"(src));
}
__device__ __forceinline__ void cp16z(uint32_t dst, const void* src, int sz) {
    asm volatile("cp.async.cg.shared.global [%0], [%1], 16, %2;"
                 :: "r"(dst), "l"(src), "r"(sz));
}
__device__ __forceinline__ void cp_commit() {
    asm volatile("cp.async.commit_group;" ::: "memory");
}
template<int N> __device__ __forceinline__ void cp_wait() {
    asm volatile("cp.async.wait_group %0;" :: "n"(N) : "memory");
}

// ============ HMMA fp16 2-pass GEMM (double-buffered cp.async, 2 blocks/SM) ============
// C[M x 256] = A[M x 256] @ (Wh + Wl)^T;  A fp16, W split fp16 [256 n][256 k].
// emode 0: C16 = fp16(acc + bias)
// emode 2: nodes(fp32) += leaky_relu(acc+bias), masked by data; y fp16 emitted pre-mask
// blockIdx.z==1 -> second problem.
__global__ void __launch_bounds__(256, 2)
gemm_mma_kernel(const __half* __restrict__ A16,
                const __half* __restrict__ wh0, const __half* __restrict__ wl0,
                const float* __restrict__ b0, void* __restrict__ C0,
                const __half* __restrict__ wh1, const __half* __restrict__ wl1,
                const float* __restrict__ b1, void* __restrict__ C1,
                int M, int emode, const int* __restrict__ data,
                __half* __restrict__ y16)
{
    extern __shared__ char smem[];
    const __half* wh = wh0; const __half* wl = wl0;
    const float* bias = b0; void* C = C0;
    if (blockIdx.z == 1) { wh = wh1; wl = wl1; bias = b1; C = C1; }

    const uint32_t sb = smem_to_u32(smem);
    const uint32_t STG = 49152;  // per-stage: A 0 | B_HI 16384 | B_LO 32768
    const int tid = threadIdx.x, lane = tid & 31, wid = tid >> 5;
    const int warpM = wid & 1, warpN = wid >> 1;
    const int m0 = blockIdx.y * 128, n0 = blockIdx.x * 128;
    const int r = tid >> 1, cb2 = (tid & 1);

    float c[4][4][4];
#pragma unroll
    for (int i = 0; i < 4; i++)
#pragma unroll
        for (int j = 0; j < 4; j++)
#pragma unroll
            for (int l = 0; l < 4; l++) c[i][j][l] = 0.f;

    auto do_stage = [&](int kc) {
        const int k0 = kc << 6;
        const uint32_t bufo = (uint32_t)(kc & 1) * STG;
        uint32_t rb = (uint32_t)r * 128u + (uint32_t)cb2 * 64u;
        {
            int grow = m0 + r;
            const __half* srcp = A16 + (size_t)grow * HH + k0 + cb2 * 32;
            int sz = (grow < M) ? 16 : 0;
#pragma unroll
            for (int i = 0; i < 4; i++)
                cp16z(sb + bufo + swz(rb + i * 16u), srcp + i * 8, sz);
        }
        {
            const __half* sh = wh + (size_t)(n0 + r) * HH + k0 + cb2 * 32;
            const __half* sl = wl + (size_t)(n0 + r) * HH + k0 + cb2 * 32;
#pragma unroll
            for (int i = 0; i < 4; i++) {
                cp_async16(sb + bufo + 16384u + swz(rb + i * 16u), sh + i * 8);
                cp_async16(sb + bufo + 32768u + swz(rb + i * 16u), sl + i * 8);
            }
        }
        cp_commit();
    };

    do_stage(0);
    do_stage(1);

    // B ldsm_x4 lane mapping: group g = lane>>3 selects matrix (nt_half = g>>1, khalf = g&1)
    const int bg = lane >> 3;
    const int b_ntoff = (bg >> 1) * 8 + (lane & 7);  // row within 2-nt pair
    const int b_kh = (bg & 1) << 4;

    for (int kc = 0; kc < 4; kc++) {
        if (kc < 3) cp_wait<1>(); else cp_wait<0>();
        __syncthreads();
        const uint32_t bufo = (uint32_t)(kc & 1) * STG;
#pragma unroll
        for (int ks = 0; ks < 4; ks++) {
            uint32_t a[4][4];
#pragma unroll
            for (int mt = 0; mt < 4; mt++) {
                int row = warpM * 64 + mt * 16 + (lane & 15);
                uint32_t off = swz((uint32_t)row * 128u + ks * 32u + ((lane >> 4) << 4));
                ldsm_x4(a[mt], sb + bufo + off);
            }
            uint32_t bh[4][2], bl[4][2];
#pragma unroll
            for (int np = 0; np < 2; np++) {
                int n = warpN * 32 + np * 16 + b_ntoff;
                uint32_t off = swz((uint32_t)n * 128u + ks * 32u + b_kh);
                uint32_t r4[4];
                ldsm_x4(r4, sb + bufo + 16384u + off);
                bh[np*2][0] = r4[0]; bh[np*2][1] = r4[1];
                bh[np*2+1][0] = r4[2]; bh[np*2+1][1] = r4[3];
                ldsm_x4(r4, sb + bufo + 32768u + off);
                bl[np*2][0] = r4[0]; bl[np*2][1] = r4[1];
                bl[np*2+1][0] = r4[2]; bl[np*2+1][1] = r4[3];
            }
#pragma unroll
            for (int mt = 0; mt < 4; mt++)
#pragma unroll
                for (int nt = 0; nt < 4; nt++) {
                    mma_fp16(c[mt][nt], a[mt], bh[nt]);
                    mma_fp16(c[mt][nt], a[mt], bl[nt]);
                }
        }
        __syncthreads();
        if (kc + 2 < 4) do_stage(kc + 2);
    }

    // ---- epilogue ----
    const int gid = lane >> 2, tig = lane & 3;
#pragma unroll
    for (int mt = 0; mt < 4; mt++)
#pragma unroll
        for (int nt = 0; nt < 4; nt++) {
            int col = n0 + warpN * 32 + nt * 8 + tig * 2;
            float bc0 = bias[col], bc1 = bias[col + 1];
#pragma unroll
            for (int h = 0; h < 2; h++) {
                int row = m0 + warpM * 64 + mt * 16 + gid + h * 8;
                if (row >= M) continue;
                float v0 = c[mt][nt][h * 2 + 0] + bc0;
                float v1 = c[mt][nt][h * 2 + 1] + bc1;
                if (emode == 2) {
                    float* crow = (float*)C + (size_t)row * HH + col;
                    float l0 = v0 > 0.f ? v0 : 0.01f * v0;
                    float l1 = v1 > 0.f ? v1 : 0.01f * v1;
                    float n0v = crow[0] + l0;
                    float n1v = crow[1] + l1;
                    bool z = (data[row] == 1);
                    *(float2*)crow = z ? make_float2(0.f, 0.f) : make_float2(n0v, n1v);
                    int b = row >> 9, ll = row & (LL - 1);
                    size_t yo = (size_t)(b * LY + 1 + ll) * HH + col;
                    *(__half2*)(y16 + yo) = __halves2half2(__float2half_rn(n0v),
                                                          __float2half_rn(n1v));
                } else {
                    *(__half2*)((__half*)C + (size_t)row * HH + col) =
                        __halves2half2(__float2half_rn(v0), __float2half_rn(v1));
                }
            }
        }
}

// ============ embedding HMMA GEMM (3-pass split-fp16, exact x0) ============
__global__ void __launch_bounds__(256, 2)
gemm_emb_mma_kernel(const int* __restrict__ data, const float* __restrict__ emb,
                    const __half* __restrict__ whE, const __half* __restrict__ wlE,
                    const float* __restrict__ bias, const float* __restrict__ pos,
                    float* __restrict__ C)
{
    extern __shared__ char smem[];
    const uint32_t sb = smem_to_u32(smem);
    const int tid = threadIdx.x, lane = tid & 31, wid = tid >> 5;
    const int warpM = wid & 1, warpN = wid >> 1;
    const int m0 = blockIdx.y * 128, n0 = blockIdx.x * 128;
    const int half = tid >> 7, r = tid & 127;

    float c[4][4][4];
#pragma unroll
    for (int i = 0; i < 4; i++)
#pragma unroll
        for (int j = 0; j < 4; j++)
#pragma unroll
            for (int l = 0; l < 4; l++) c[i][j][l] = 0.f;

    const int bg = lane >> 3;
    const int b_ntoff = (bg >> 1) * 8 + (lane & 7);
    const int b_kh = (bg & 1) << 4;

    for (int kc = 0; kc < 5; kc++) {
        const int k0 = kc << 6;
        {
            int grow = m0 + r;
            const float* srow = emb + (size_t)data[grow] * E_DIM;
            char* dbase = smem + half * 16384;
            uint32_t rb = (uint32_t)r * 128u;
#pragma unroll
            for (int i = 0; i < 8; i++) {
                union { uint4 u; unsigned short s[8]; } pk;
#pragma unroll
                for (int j = 0; j < 8; j++) {
                    int kk = k0 + i * 8 + j;
                    float f = (kk < E_DIM) ? srow[kk] : 0.f;
                    __half h, l;
                    split_fp16(f, h, l);
                    pk.s[j] = __half_as_ushort(half ? l : h);
                }
                *(uint4*)(dbase + swz(rb + i * 16u)) = pk.u;
            }
        }
        {
            const __half* srcp = (half ? wlE : whE) + (size_t)(n0 + r) * 320 + k0;
            char* dbase = smem + 32768 + half * 16384;
            uint32_t rb = (uint32_t)r * 128u;
#pragma unroll
            for (int i = 0; i < 8; i++)
                *(uint4*)(dbase + swz(rb + i * 16u)) = *(const uint4*)(srcp + i * 8);
        }
        __syncthreads();
#pragma unroll
        for (int ks = 0; ks < 4; ks++) {
            uint32_t ah[4][4], al[4][4];
#pragma unroll
            for (int mt = 0; mt < 4; mt++) {
                int row = warpM * 64 + mt * 16 + (lane & 15);
                uint32_t off = swz((uint32_t)row * 128u + ks * 32u + ((lane >> 4) << 4));
                ldsm_x4(ah[mt], sb + off);
                ldsm_x4(al[mt], sb + 16384u + off);
            }
            uint32_t bh[4][2], bl[4][2];
#pragma unroll
            for (int np = 0; np < 2; np++) {
                int n = warpN * 32 + np * 16 + b_ntoff;
                uint32_t off = swz((uint32_t)n * 128u + ks * 32u + b_kh);
                uint32_t r4[4];
                ldsm_x4(r4, sb + 32768u + off);
                bh[np*2][0] = r4[0]; bh[np*2][1] = r4[1];
                bh[np*2+1][0] = r4[2]; bh[np*2+1][1] = r4[3];
                ldsm_x4(r4, sb + 49152u + off);
                bl[np*2][0] = r4[0]; bl[np*2][1] = r4[1];
                bl[np*2+1][0] = r4[2]; bl[np*2+1][1] = r4[3];
            }
#pragma unroll
            for (int mt = 0; mt < 4; mt++)
#pragma unroll
                for (int nt = 0; nt < 4; nt++) {
                    mma_fp16(c[mt][nt], ah[mt], bh[nt]);
                    mma_fp16(c[mt][nt], ah[mt], bl[nt]);
                    mma_fp16(c[mt][nt], al[mt], bh[nt]);
                }
        }
        __syncthreads();
    }

    const int gid = lane >> 2, tig = lane & 3;
#pragma unroll
    for (int mt = 0; mt < 4; mt++)
#pragma unroll
        for (int nt = 0; nt < 4; nt++) {
            int col = n0 + warpN * 32 + nt * 8 + tig * 2;
            float bc0 = bias[col], bc1 = bias[col + 1];
#pragma unroll
            for (int h = 0; h < 2; h++) {
                int row = m0 + warpM * 64 + mt * 16 + gid + h * 8;
                int pr = (row & (LL - 1)) * HH + col;
                float v0 = c[mt][nt][h * 2 + 0] + bc0 + pos[pr];
                float v1 = c[mt][nt][h * 2 + 1] + bc1 + pos[pr + 1];
                *(float2*)&C[(size_t)row * HH + col] = make_float2(v0, v1);
            }
        }
}

// ============ weight prep: coalesced tiled transpose + fp16 split ============
__global__ void prep_w_kernel(const float* __restrict__ rWQ, const float* __restrict__ rWK,
                              const float* __restrict__ rWO, const float* __restrict__ sWK,
                              const float* __restrict__ sWV, const float* __restrict__ embW,
                              __half* __restrict__ whi, __half* __restrict__ wlo,
                              __half* __restrict__ whiE, __half* __restrict__ wloE)
{
    int slot = blockIdx.z;
    int n0 = blockIdx.x * 32, k0 = blockIdx.y * 32;
    const float* W; int K, Kpad;
    __half *oh, *ol;
    if (slot < 30) {
        if (k0 >= 256) return;
        int fam = slot / 6, it = slot % 6;
        W = (fam == 0 ? rWQ : fam == 1 ? rWK : fam == 2 ? rWO :
             fam == 3 ? sWK : sWV) + (size_t)it * HH * HH;
        K = 256; Kpad = 256;
        oh = whi + (size_t)slot * 65536; ol = wlo + (size_t)slot * 65536;
    } else {
        W = embW; K = E_DIM; Kpad = 320; oh = whiE; ol = wloE;
    }
    __shared__ float tile[32][33];
    int tx = threadIdx.x, ty = threadIdx.y;
#pragma unroll
    for (int i = 0; i < 4; i++) {
        int k = k0 + ty + i * 8;
        tile[ty + i * 8][tx] = (k < K) ? W[(size_t)k * HH + n0 + tx] : 0.f;
    }
    __syncthreads();
#pragma unroll
    for (int i = 0; i < 4; i++) {
        int n = n0 + ty + i * 8;
        float x = tile[tx][ty + i * 8];
        __half h, l;
        split_fp16(x, h, l);
        size_t o = (size_t)n * Kpad + k0 + tx;
        oh[o] = h; ol[o] = l;
    }
}

// ---------------- fused: layernorm (blocks 0..2047) + relay projections (2048..2175) ----
__global__ void __launch_bounds__(256)
ln_rp4_kernel(const float* __restrict__ x, __half* __restrict__ nln16,
              const float* __restrict__ g, const float* __restrict__ b,
              const float* __restrict__ relay,
              const float* __restrict__ WK, const float* __restrict__ bK, float* __restrict__ ak,
              const float* __restrict__ WV, const float* __restrict__ bV, float* __restrict__ av,
              const float* __restrict__ sWQ, const float* __restrict__ sbQ, float* __restrict__ q2,
              __half* __restrict__ y16)
{
    if (blockIdx.x >= 2048) {
        int idx = blockIdx.x - 2048;
        int seg = idx >> 5, bb = idx & 31, t = threadIdx.x;
        if (seg == 3) {
            y16[(size_t)(bb * LY) * HH + t] = __float2half_rn(relay[bb * HH + t]);
            return;
        }
        const float* W  = seg == 0 ? WK : seg == 1 ? WV : sWQ;
        const float* bi = seg == 0 ? bK : seg == 1 ? bV : sbQ;
        float* o        = seg == 0 ? ak : seg == 1 ? av : q2;
        __shared__ float xin[HH];
        xin[t] = relay[bb * HH + t];
        __syncthreads();
        float s = bi[t];
#pragma unroll 8
        for (int k = 0; k < HH; k++) s += xin[k] * W[k * HH + t];
        o[bb * HH + t] = s;
        return;
    }
    int w = threadIdx.x >> 5, lane = threadIdx.x & 31;
    int row = blockIdx.x * 8 + w;
    const float* xr = x + (size_t)row * HH;
    float4 v0 = *(const float4*)&xr[lane * 4];
    float4 v1 = *(const float4*)&xr[lane * 4 + 128];
    float s = v0.x + v0.y + v0.z + v0.w + v1.x + v1.y + v1.z + v1.w;
    float mean = warpReduceSum(s) * (1.f / HH);
    float d[8] = { v0.x - mean, v0.y - mean, v0.z - mean, v0.w - mean,
                   v1.x - mean, v1.y - mean, v1.z - mean, v1.w - mean };
    float s2 = 0.f;
#pragma unroll
    for (int i = 0; i < 8; i++) s2 += d[i] * d[i];
    float var = warpReduceSum(s2) * (1.f / HH);
    float rs = rsqrtf(var + 1e-5f);
    float4 g0 = *(const float4*)&g[lane * 4];
    float4 g1 = *(const float4*)&g[lane * 4 + 128];
    float4 bb0 = *(const float4*)&b[lane * 4];
    float4 bb1 = *(const float4*)&b[lane * 4 + 128];
    float o[8] = { g0.x*d[0]*rs + bb0.x, g0.y*d[1]*rs + bb0.y,
                   g0.z*d[2]*rs + bb0.z, g0.w*d[3]*rs + bb0.w,
                   g1.x*d[4]*rs + bb1.x, g1.y*d[5]*rs + bb1.y,
                   g1.z*d[6]*rs + bb1.z, g1.w*d[7]*rs + bb1.w };
#pragma unroll
    for (int seg = 0; seg < 2; seg++) {
        ushort4 hv;
        hv.x = __half_as_ushort(__float2half_rn(o[seg*4+0]));
        hv.y = __half_as_ushort(__float2half_rn(o[seg*4+1]));
        hv.z = __half_as_ushort(__float2half_rn(o[seg*4+2]));
        hv.w = __half_as_ushort(__float2half_rn(o[seg*4+3]));
        *(ushort4*)(nln16 + (size_t)row * HH + lane * 4 + seg * 128) = hv;
    }
}

// ---------------- relay = mean over L ----------------
__global__ void __launch_bounds__(256)
relay_mean_kernel(const float* __restrict__ x0, float* __restrict__ relay)
{
    int b = blockIdx.x;
    int tx = threadIdx.x & 63, ty = threadIdx.x >> 6;
    float4 acc = make_float4(0.f, 0.f, 0.f, 0.f);
    for (int l = ty; l < LL; l += 4) {
        float4 v = *(const float4*)&x0[(size_t)(b * LL + l) * HH + tx * 4];
        acc.x += v.x; acc.y += v.y; acc.z += v.z; acc.w += v.w;
    }
    __shared__ float4 part[4][64];
    part[ty][tx] = acc;
    __syncthreads();
    if (ty == 0) {
        float4 s = part[0][tx];
#pragma unroll
        for (int i = 1; i < 4; i++) {
            s.x += part[i][tx].x; s.y += part[i][tx].y;
            s.z += part[i][tx].z; s.w += part[i][tx].w;
        }
        const float inv = 1.f / LL;
        *(float4*)&relay[b * HH + tx * 4] =
            make_float4(s.x * inv, s.y * inv, s.z * inv, s.w * inv);
    }
}

__global__ void rowproj_kernel(const float* __restrict__ in, const float* __restrict__ W,
                               const float* __restrict__ bias, float* __restrict__ out,
                               int lrelu)
{
    __shared__ float xin[HH];
    int b = blockIdx.x, t = threadIdx.x;
    xin[t] = in[b * HH + t];
    __syncthreads();
    float s = bias[t];
#pragma unroll 8
    for (int k = 0; k < HH; k++) s += xin[k] * W[k * HH + t];
    if (lrelu) s = s > 0.f ? s : 0.01f * s;
    out[b * HH + t] = s;
}

// ---------------- msa1: 8 rows/block, smem-staged sliding k window ----------------
__global__ void __launch_bounds__(256)
msa1_attn_kernel(const __half* __restrict__ q16, const __half* __restrict__ k16,
                 const float* __restrict__ ak, const float* __restrict__ av,
                 __half* __restrict__ att16)
{
    __shared__ __half ks[10][HH];
    __shared__ __half qs[8][HH];
    __shared__ float aks[HH], avs[HH];
    int r0 = blockIdx.x * 8;
    int b = r0 >> 9, l0 = r0 & (LL - 1);
    int t = threadIdx.x;
    for (int id = t; id < 10 * 128; id += 256) {
        int i = id >> 7, cu = id & 127;
        int gr = r0 - 1 + i;
        gr = gr < 0 ? 0 : (gr > BB * LL - 1 ? BB * LL - 1 : gr);
        ((uint32_t*)ks[i])[cu] = ((const uint32_t*)(k16 + (size_t)gr * HH))[cu];
    }
    for (int id = t; id < 8 * 128; id += 256) {
        int i = id >> 7, cu = id & 127;
        ((uint32_t*)qs[i])[cu] = ((const uint32_t*)(q16 + (size_t)(r0 + i) * HH))[cu];
    }
    aks[t] = ak[b * HH + t];
    avs[t] = av[b * HH + t];
    __syncthreads();
    int c = t;
    float akv = aks[c], avv = avs[c];
    const float sc = 0.17677669529663687f;
#pragma unroll
    for (int rr = 0; rr < 8; rr++) {
        int l = l0 + rr;
        float qv  = __half2float(qs[rr][c]);
        float k0v = __half2float(ks[rr + 1][c]);
        float kmv = (l > 0)      ? __half2float(ks[rr][c])     : 0.f;
        float kpv = (l < LL - 1) ? __half2float(ks[rr + 2][c]) : 0.f;
        float s0 = warpReduceSum(qv * akv) * sc;
        float s1 = warpReduceSum(qv * kmv) * sc;
        float s2 = warpReduceSum(qv * k0v) * sc;
        float s3 = warpReduceSum(qv * kpv) * sc;
        float m = fmaxf(fmaxf(s0, s1), fmaxf(s2, s3));
        float e0 = expf(s0 - m), e1 = expf(s1 - m), e2 = expf(s2 - m), e3 = expf(s3 - m);
        float inv = 1.f / (e0 + e1 + e2 + e3);
        float o = (e0 * avv + e1 * kmv + e2 * k0v + e3 * kpv) * inv;
        att16[(size_t)(r0 + rr) * HH + c] = __float2half_rn(o);
    }
}

// ---------------- msa2 (fp16 yk/yv) ----------------
__global__ void __launch_bounds__(256)
msa2_attn_kernel(const float* __restrict__ q2, const __half* __restrict__ yk,
                 const __half* __restrict__ yv, float* __restrict__ att2)
{
    __shared__ float sc[LY];
    __shared__ float red[8];
    __shared__ float part[8][HD];
    int b = blockIdx.x >> 3, h = blockIdx.x & 7;
    int t = threadIdx.x, w = t >> 5, d = t & 31;
    const float scale = 0.17677669529663687f;
    float qv = q2[b * HH + h * HD + d];
    const __half* kb = yk + (size_t)b * LY * HH + h * HD;
    const __half* vb = yv + (size_t)b * LY * HH + h * HD;
    for (int l = w; l < LY; l += 8) {
        float s = warpReduceSum(qv * __half2float(kb[(size_t)l * HH + d])) * scale;
        if (d == 0) sc[l] = s;
    }
    __syncthreads();
    float m = -3.4e38f;
    for (int l = t; l < LY; l += 256) m = fmaxf(m, sc[l]);
#pragma unroll
    for (int o = 16; o > 0; o >>= 1) m = fmaxf(m, __shfl_xor_sync(0xffffffffu, m, o));
    if (d == 0) red[w] = m;
    __syncthreads();
    float mm = red[0];
#pragma unroll
    for (int i = 1; i < 8; i++) mm = fmaxf(mm, red[i]);
    __syncthreads();
    float ssum = 0.f;
    for (int l = t; l < LY; l += 256) { float e = expf(sc[l] - mm); sc[l] = e; ssum += e; }
    ssum = warpReduceSum(ssum);
    if (d == 0) red[w] = ssum;
    __syncthreads();
    float tot = 0.f;
#pragma unroll
    for (int i = 0; i < 8; i++) tot += red[i];
    float acc = 0.f;
    for (int l = w; l < LY; l += 8) acc += sc[l] * __half2float(vb[(size_t)l * HH + d]);
    part[w][d] = acc;
    __syncthreads();
    if (w == 0) {
        float o = 0.f;
#pragma unroll
        for (int i = 0; i < 8; i++) o += part[i][d];
        att2[b * HH + h * HD + d] = o / tot;
    }
}

// ---------------- final: 0.5*max_l(nodes) + 0.5*relay ----------------
__global__ void __launch_bounds__(256)
final_kernel(const float* __restrict__ nodes, const float* __restrict__ relay,
             float* __restrict__ out)
{
    int b = blockIdx.x;
    int tx = threadIdx.x & 63, ty = threadIdx.x >> 6;
    float4 m = make_float4(-3.4e38f, -3.4e38f, -3.4e38f, -3.4e38f);
    for (int l = ty; l < LL; l += 4) {
        float4 v = *(const float4*)&nodes[(size_t)(b * LL + l) * HH + tx * 4];
        m.x = fmaxf(m.x, v.x); m.y = fmaxf(m.y, v.y);
        m.z = fmaxf(m.z, v.z); m.w = fmaxf(m.w, v.w);
    }
    __shared__ float4 part[4][64];
    part[ty][tx] = m;
    __syncthreads();
    if (ty == 0) {
        float4 s = part[0][tx];
#pragma unroll
        for (int i = 1; i < 4; i++) {
            s.x = fmaxf(s.x, part[i][tx].x); s.y = fmaxf(s.y, part[i][tx].y);
            s.z = fmaxf(s.z, part[i][tx].z); s.w = fmaxf(s.w, part[i][tx].w);
        }
        float4 r = *(const float4*)&relay[b * HH + tx * 4];
        *(float4*)&out[b * HH + tx * 4] =
            make_float4(0.5f * s.x + 0.5f * r.x, 0.5f * s.y + 0.5f * r.y,
                        0.5f * s.z + 0.5f * r.z, 0.5f * s.w + 0.5f * r.w);
    }
}

// ---------------- host ----------------
extern "C" void kernel_launch(void* const* d_in, const int* in_sizes, int n_in,
                              void* d_out, int out_size)
{
    const int*   data     = (const int*)  d_in[0];
    const float* emb      = (const float*)d_in[1];
    const float* emb_fc_W = (const float*)d_in[2];
    const float* emb_fc_b = (const float*)d_in[3];
    const float* pos_emb  = (const float*)d_in[4];
    const float* ln_g     = (const float*)d_in[5];
    const float* ln_b     = (const float*)d_in[6];
    const float* r_WQ = (const float*)d_in[7];
    const float* r_bQ = (const float*)d_in[8];
    const float* r_WK = (const float*)d_in[9];
    const float* r_bK = (const float*)d_in[10];
    const float* r_WV = (const float*)d_in[11];
    const float* r_bV = (const float*)d_in[12];
    const float* r_WO = (const float*)d_in[13];
    const float* r_bO = (const float*)d_in[14];
    const float* s_WQ = (const float*)d_in[15];
    const float* s_bQ = (const float*)d_in[16];
    const float* s_WK = (const float*)d_in[17];
    const float* s_bK = (const float*)d_in[18];
    const float* s_WV = (const float*)d_in[19];
    const float* s_bV = (const float*)d_in[20];
    const float* s_WO = (const float*)d_in[21];
    const float* s_bO = (const float*)d_in[22];
    float* out = (float*)d_out;
    (void)in_sizes; (void)n_in; (void)out_size;

    float *nodes, *relay, *ak, *av, *q2, *att2;
    __half *q16, *k16, *yk16, *yv16;
    __half *w16h, *w16l, *wEh, *wEl, *nln16, *att16, *y16;
    cudaGetSymbolAddress((void**)&nodes, g_nodes);
    cudaGetSymbolAddress((void**)&relay, g_relay);
    cudaGetSymbolAddress((void**)&ak,    g_ak);
    cudaGetSymbolAddress((void**)&av,    g_av);
    cudaGetSymbolAddress((void**)&q2,    g_q2);
    cudaGetSymbolAddress((void**)&att2,  g_att2);
    cudaGetSymbolAddress((void**)&q16,   g_q16);
    cudaGetSymbolAddress((void**)&k16,   g_k16);
    cudaGetSymbolAddress((void**)&yk16,  g_yk16);
    cudaGetSymbolAddress((void**)&yv16,  g_yv16);
    cudaGetSymbolAddress((void**)&w16h,  g_w16h);
    cudaGetSymbolAddress((void**)&w16l,  g_w16l);
    cudaGetSymbolAddress((void**)&wEh,   g_wEh);
    cudaGetSymbolAddress((void**)&wEl,   g_wEl);
    cudaGetSymbolAddress((void**)&nln16, g_nln16);
    cudaGetSymbolAddress((void**)&att16, g_att16);
    cudaGetSymbolAddress((void**)&y16,   g_y16);

    const int M1 = BB * LL;    // 16384
    const int M2 = BB * LY;    // 16416
    const int MMA_SMEM  = 98304;   // 2 x 48KB stages -> 2 blocks/SM
    const int EMB_SMEM  = 65536;
    static int attr_done = 0;
    if (!attr_done) {
        cudaFuncSetAttribute(gemm_mma_kernel,
                             cudaFuncAttributeMaxDynamicSharedMemorySize, MMA_SMEM);
        cudaFuncSetAttribute(gemm_emb_mma_kernel,
                             cudaFuncAttributeMaxDynamicSharedMemorySize, EMB_SMEM);
        attr_done = 1;
    }

    dim3 blk(256);
    auto WHp = [&](int slot) { return w16h + (size_t)slot * 65536; };
    auto WLp = [&](int slot) { return w16l + (size_t)slot * 65536; };

    // prep split-transposed weights (Q=0..5, K=6..11, O=12..17, sK=18..23, sV=24..29, emb=30)
    prep_w_kernel<<<dim3(8, 10, 31), dim3(32, 8)>>>(r_WQ, r_WK, r_WO, s_WK, s_WV, emb_fc_W,
                                                    w16h, w16l, wEh, wEl);

    // x0 = emb[data] @ emb_fc_W + b + pos ; relay = mean_L(x0)
    gemm_emb_mma_kernel<<<dim3(2, 128), blk, EMB_SMEM>>>(data, emb, wEh, wEl,
                                                         emb_fc_b, pos_emb, nodes);
    relay_mean_kernel<<<BB, blk>>>(nodes, relay);

    for (int i = 0; i < ITERS; i++) {
        const float* bQ = r_bQ + i * HH;
        const float* bK = r_bK + i * HH;
        const float* WK = r_WK + i * HH * HH;
        const float* WV = r_WV + i * HH * HH;
        const float* bV = r_bV + i * HH;
        const float* bO = r_bO + i * HH;
        const float* sWQ = s_WQ + i * HH * HH; const float* sbQ = s_bQ + i * HH;
        const float* sbK = s_bK + i * HH;
        const float* sbV = s_bV + i * HH;
        const float* sWO = s_WO + i * HH * HH; const float* sbO = s_bO + i * HH;

        // fused layernorm + (ak, av, q2, relay->y row)
        ln_rp4_kernel<<<2048 + 128, blk>>>(nodes, nln16, ln_g + i * HH, ln_b + i * HH,
                                           relay, WK, bK, ak, WV, bV, av,
                                           sWQ, sbQ, q2, y16);
        // fused Q + K projections (2-pass fp16)
        gemm_mma_kernel<<<dim3(2, 128, 2), blk, MMA_SMEM>>>(
            nln16, WHp(i), WLp(i), bQ, q16, WHp(6 + i), WLp(6 + i), bK, k16,
            M1, 0, nullptr, nullptr);
        msa1_attn_kernel<<<M1 / 8, blk>>>(q16, k16, ak, av, att16);
        // O projection + leaky residual + mask + y emit
        gemm_mma_kernel<<<dim3(2, 128, 1), blk, MMA_SMEM>>>(
            att16, WHp(12 + i), WLp(12 + i), bO, nodes,
            nullptr, nullptr, nullptr, nullptr,
            M1, 2, data, y16);
        // fused yK + yV
        gemm_mma_kernel<<<dim3(2, 129, 2), blk, MMA_SMEM>>>(
            y16, WHp(18 + i), WLp(18 + i), sbK, yk16,
            WHp(24 + i), WLp(24 + i), sbV, yv16,
            M2, 0, nullptr, nullptr);
        msa2_attn_kernel<<<BB * NH, blk>>>(q2, yk16, yv16, att2);
        rowproj_kernel<<<BB, HH>>>(att2, sWO, sbO, relay, 1);
    }
    final_kernel<<<BB, blk>>>(nodes, relay, out);
}